// round 13
// baseline (speedup 1.0000x reference)
#include <cuda_runtime.h>
#include <cuda_bf16.h>
#include <math.h>
#include <stdint.h>

// Problem constants
#define BB    4
#define QQ    2048
#define KVN   2048
#define DD    512
#define UQ    60
#define NTILES (KVN / 128)       // 16
#define WS_SPLIT 32
#define KVC   (KVN / WS_SPLIT)   // 64
#define PVS   32
#define CHUNK 32
#define NSTAGE (DD / CHUNK)      // 16
#define WWIN  1.0f               // rescue window (6-sigma bf16 dot err ~0.4)

// ---------------- scratch ----------------------------------------------------
__device__ int   g_count[BB * KVN];
__device__ float g_wspart[WS_SPLIT * BB * DD];
__device__ float g_vmpart[WS_SPLIT * BB * DD];
__device__ float g_wsum[BB * DD];
__device__ float g_vmean[BB * DD];
__device__ float g_M[BB * QQ];
__device__ float g_Mpart[BB * QQ * NTILES];
__device__ uint32_t g_cand[(size_t)BB * QQ * NTILES * 4];
__device__ int   g_topidx[BB * UQ];
__device__ float g_S1[(size_t)BB * UQ * KVN];
__device__ float g_Opart[(size_t)PVS * BB * UQ * DD];
__device__ __nv_bfloat16 g_qhi[(size_t)BB * QQ * DD];
__device__ __nv_bfloat16 g_khi[(size_t)BB * KVN * DD];

// ---------------- PTX helpers -------------------------------------------------
__device__ __forceinline__ uint32_t smem_u32(const void* p) {
    return (uint32_t)__cvta_generic_to_shared(p);
}
__device__ __forceinline__ void cpa16(uint32_t saddr, const void* g) {
    asm volatile("cp.async.cg.shared.global [%0], [%1], 16;" :: "r"(saddr), "l"(g));
}
__device__ __forceinline__ void ldsm4(uint32_t& r0, uint32_t& r1, uint32_t& r2,
                                      uint32_t& r3, uint32_t addr) {
    asm volatile("ldmatrix.sync.aligned.m8n8.x4.shared.b16 {%0,%1,%2,%3}, [%4];"
                 : "=r"(r0), "=r"(r1), "=r"(r2), "=r"(r3) : "r"(addr));
}
__device__ __forceinline__ void mma16816(float* c, const uint32_t* a,
                                         uint32_t b0, uint32_t b1) {
    asm volatile(
        "mma.sync.aligned.m16n8k16.row.col.f32.bf16.bf16.f32 "
        "{%0,%1,%2,%3}, {%4,%5,%6,%7}, {%8,%9}, {%0,%1,%2,%3};"
        : "+f"(c[0]), "+f"(c[1]), "+f"(c[2]), "+f"(c[3])
        : "r"(a[0]), "r"(a[1]), "r"(a[2]), "r"(a[3]), "r"(b0), "r"(b1));
}

// ---------------- kernel 0: bf16 hi of q and k ---------------------------------
__global__ void split_kernel(const float* __restrict__ q, const float* __restrict__ k) {
    size_t i = (size_t)blockIdx.x * 256 + threadIdx.x;   // float4 index
    float4 a = ((const float4*)q)[i];
    __nv_bfloat162 h01, h23;
    h01.x = __float2bfloat16(a.x); h01.y = __float2bfloat16(a.y);
    h23.x = __float2bfloat16(a.z); h23.y = __float2bfloat16(a.w);
    ((__nv_bfloat162*)g_qhi)[i * 2] = h01; ((__nv_bfloat162*)g_qhi)[i * 2 + 1] = h23;

    float4 bvec = ((const float4*)k)[i];
    h01.x = __float2bfloat16(bvec.x); h01.y = __float2bfloat16(bvec.y);
    h23.x = __float2bfloat16(bvec.z); h23.y = __float2bfloat16(bvec.w);
    ((__nv_bfloat162*)g_khi)[i * 2] = h01; ((__nv_bfloat162*)g_khi)[i * 2 + 1] = h23;
}

// ---------------- kernels 1,2: counts -----------------------------------------
__global__ void zero_count_kernel() {
    int i = blockIdx.x * blockDim.x + threadIdx.x;
    if (i < BB * KVN) g_count[i] = 0;
}
__global__ void count_kernel(const int* __restrict__ sidx, int U) {
    int i = blockIdx.x * blockDim.x + threadIdx.x;
    if (i < BB * U) {
        int b = i / U;
        atomicAdd(&g_count[b * KVN + sidx[i]], 1);
    }
}

// ---------------- kernel 3: weighted key sum + v mean (float4 per thread) ------
// grid (WS_SPLIT, BB), block 128: thread t owns float4 column t (d = 4t..4t+3).
__global__ void wsum_part_kernel(const float* __restrict__ k,
                                 const float* __restrict__ v) {
    int s = blockIdx.x;
    int b = blockIdx.y;
    int d4 = threadIdx.x;          // float4 index 0..127

    __shared__ float cntf[KVC];
    if (threadIdx.x < KVC)
        cntf[threadIdx.x] = (float)g_count[b * KVN + s * KVC + threadIdx.x];
    __syncthreads();

    const float4* kp = (const float4*)(k + ((size_t)b * KVN + (size_t)s * KVC) * DD) + d4;
    const float4* vp = (const float4*)(v + ((size_t)b * KVN + (size_t)s * KVC) * DD) + d4;
    float4 ws = make_float4(0.f, 0.f, 0.f, 0.f);
    float4 vm = make_float4(0.f, 0.f, 0.f, 0.f);
#pragma unroll 8
    for (int j = 0; j < KVC; j++) {
        float c = cntf[j];
        float4 kv = kp[(size_t)j * (DD / 4)];
        float4 vv = vp[(size_t)j * (DD / 4)];
        ws.x += c * kv.x; ws.y += c * kv.y; ws.z += c * kv.z; ws.w += c * kv.w;
        vm.x += vv.x;     vm.y += vv.y;     vm.z += vv.z;     vm.w += vv.w;
    }
    ((float4*)g_wspart)[((size_t)s * BB + b) * (DD / 4) + d4] = ws;
    ((float4*)g_vmpart)[((size_t)s * BB + b) * (DD / 4) + d4] = vm;
}

// float4 over d: 8 blocks x 64 threads cover BB*DD/4 vectors
__global__ void wsum_reduce_kernel() {
    int idx = blockIdx.x * 64 + threadIdx.x;   // 0..511
    if (idx >= BB * DD / 4) return;
    float4 ws = make_float4(0.f, 0.f, 0.f, 0.f);
    float4 vm = make_float4(0.f, 0.f, 0.f, 0.f);
#pragma unroll
    for (int s = 0; s < WS_SPLIT; s++) {
        float4 a = ((const float4*)g_wspart)[(size_t)s * (BB * DD / 4) + idx];
        float4 c = ((const float4*)g_vmpart)[(size_t)s * (BB * DD / 4) + idx];
        ws.x += a.x; ws.y += a.y; ws.z += a.z; ws.w += a.w;
        vm.x += c.x; vm.y += c.y; vm.z += c.z; vm.w += c.w;
    }
    ((float4*)g_wsum)[idx] = ws;
    vm.x *= (1.0f / KVN); vm.y *= (1.0f / KVN);
    vm.z *= (1.0f / KVN); vm.w *= (1.0f / KVN);
    ((float4*)g_vmean)[idx] = vm;
}

// ---------------- kernel 4: approx QK^T (bf16 HMMA) -> rowmax + cand bits ------
__global__ void __launch_bounds__(256, 2)
qkmax_tc_kernel() {
    __shared__ __nv_bfloat16 sA[3][128][40];
    __shared__ __nv_bfloat16 sB[3][128][40];
    __shared__ int      cmask[128];
    __shared__ float    smax[128][4];
    __shared__ float    rmax[128];
    __shared__ uint32_t bits[128][4];

    const int tid = threadIdx.x, lane = tid & 31, warp = tid >> 5;
    const int wm = warp >> 2, wn = warp & 3;
    const int b = blockIdx.z;
    const int m0 = blockIdx.x * 128, n0 = blockIdx.y * 128;

    const __nv_bfloat16* qh = g_qhi + (size_t)b * QQ * DD;
    const __nv_bfloat16* kh = g_khi + (size_t)b * KVN * DD;

    if (tid < 128) {
        cmask[tid] = g_count[b * KVN + n0 + tid];
        bits[tid][0] = 0u; bits[tid][1] = 0u; bits[tid][2] = 0u; bits[tid][3] = 0u;
    }

    const int lrow = tid >> 1, lhalf = tid & 1;
    const size_t gaoff = (size_t)(m0 + lrow) * DD + lhalf * 8;
    const size_t gboff = (size_t)(n0 + lrow) * DD + lhalf * 8;
    const uint32_t saA = smem_u32(&sA[0][lrow][lhalf * 8]);
    const uint32_t saB = smem_u32(&sB[0][lrow][lhalf * 8]);
    const uint32_t BUFSTRIDE = 128 * 40 * 2;

    const int lr = lane & 15;
    const int lc8 = (lane >> 4) * 8;
    const uint32_t aAh = smem_u32(&sA[0][wm * 64 + lr][lc8]);
    const uint32_t aBh = smem_u32(&sB[0][wn * 32 + lr][lc8]);

    float acc[4][4][4];
#pragma unroll
    for (int mt = 0; mt < 4; mt++)
#pragma unroll
        for (int nt = 0; nt < 4; nt++)
#pragma unroll
            for (int r = 0; r < 4; r++) acc[mt][nt][r] = 0.f;

    auto issue = [&](int ks) {
        uint32_t bo = (uint32_t)(ks % 3) * BUFSTRIDE;
        int dt = ks * CHUNK;
        cpa16(saA + bo,      qh + gaoff + dt);
        cpa16(saA + bo + 32, qh + gaoff + dt + 16);
        cpa16(saB + bo,      kh + gboff + dt);
        cpa16(saB + bo + 32, kh + gboff + dt + 16);
        asm volatile("cp.async.commit_group;");
    };

    issue(0);
    issue(1);
#pragma unroll 1
    for (int ks = 0; ks < NSTAGE; ks++) {
        if (ks < NSTAGE - 1)
            asm volatile("cp.async.wait_group 1;");
        else
            asm volatile("cp.async.wait_group 0;");
        __syncthreads();
        if (ks + 2 < NSTAGE) issue(ks + 2);

        uint32_t bo = (uint32_t)(ks % 3) * BUFSTRIDE;
#pragma unroll
        for (int kh2 = 0; kh2 < 2; kh2++) {
            uint32_t ko = bo + kh2 * 32;
            uint32_t a[4][4], bf[2][4];
#pragma unroll
            for (int mt = 0; mt < 4; mt++)
                ldsm4(a[mt][0], a[mt][1], a[mt][2], a[mt][3], aAh + ko + mt * 1280);
#pragma unroll
            for (int nc = 0; nc < 2; nc++)
                ldsm4(bf[nc][0], bf[nc][1], bf[nc][2], bf[nc][3], aBh + ko + nc * 1280);
#pragma unroll
            for (int mt = 0; mt < 4; mt++)
#pragma unroll
                for (int nt = 0; nt < 4; nt++) {
                    int nc = nt >> 1, s = nt & 1;
                    mma16816(acc[mt][nt], a[mt], bf[nc][s], bf[nc][2 + s]);
                }
        }
    }

#pragma unroll
    for (int nt = 0; nt < 4; nt++) {
        int c = wn * 32 + nt * 8 + (lane & 3) * 2;
        bool ok0 = cmask[c] > 0, ok1 = cmask[c + 1] > 0;
#pragma unroll
        for (int mt = 0; mt < 4; mt++) {
            if (!ok0) { acc[mt][nt][0] = -3.0e38f; acc[mt][nt][2] = -3.0e38f; }
            if (!ok1) { acc[mt][nt][1] = -3.0e38f; acc[mt][nt][3] = -3.0e38f; }
        }
    }
    float rm[8];
#pragma unroll
    for (int i = 0; i < 8; i++) rm[i] = -3.0e38f;
#pragma unroll
    for (int nt = 0; nt < 4; nt++)
#pragma unroll
        for (int mt = 0; mt < 4; mt++) {
            rm[mt * 2]     = fmaxf(rm[mt * 2],     fmaxf(acc[mt][nt][0], acc[mt][nt][1]));
            rm[mt * 2 + 1] = fmaxf(rm[mt * 2 + 1], fmaxf(acc[mt][nt][2], acc[mt][nt][3]));
        }
#pragma unroll
    for (int i = 0; i < 8; i++) {
        rm[i] = fmaxf(rm[i], __shfl_xor_sync(0xffffffffu, rm[i], 1));
        rm[i] = fmaxf(rm[i], __shfl_xor_sync(0xffffffffu, rm[i], 2));
    }
    if ((lane & 3) == 0) {
        int g = lane >> 2;
#pragma unroll
        for (int mt = 0; mt < 4; mt++) {
            smax[wm * 64 + mt * 16 + g][wn]     = rm[mt * 2];
            smax[wm * 64 + mt * 16 + g + 8][wn] = rm[mt * 2 + 1];
        }
    }
    __syncthreads();
    if (tid < 128)
        rmax[tid] = fmaxf(fmaxf(smax[tid][0], smax[tid][1]),
                          fmaxf(smax[tid][2], smax[tid][3]));
    __syncthreads();

    {
        int g = lane >> 2;
#pragma unroll
        for (int mt = 0; mt < 4; mt++) {
            int r0 = wm * 64 + mt * 16 + g;
            float t0 = rmax[r0] - WWIN, t1 = rmax[r0 + 8] - WWIN;
#pragma unroll
            for (int nt = 0; nt < 4; nt++) {
                int c = wn * 32 + nt * 8 + (lane & 3) * 2;
                if (acc[mt][nt][0] >= t0) atomicOr(&bits[r0][c >> 5], 1u << (c & 31));
                if (acc[mt][nt][1] >= t0) atomicOr(&bits[r0][(c + 1) >> 5], 1u << ((c + 1) & 31));
                if (acc[mt][nt][2] >= t1) atomicOr(&bits[r0 + 8][c >> 5], 1u << (c & 31));
                if (acc[mt][nt][3] >= t1) atomicOr(&bits[r0 + 8][(c + 1) >> 5], 1u << ((c + 1) & 31));
            }
        }
    }
    __syncthreads();
    if (tid < 128) {
        size_t ro = ((size_t)b * QQ + m0 + tid) * NTILES + blockIdx.y;
        g_Mpart[ro] = rmax[tid];
        *(uint4*)&g_cand[ro * 4] = *(uint4*)&bits[tid][0];
    }
}

// ---------------- kernel 5: refine — exact max + M -----------------------------
__global__ void refine_kernel(const float* __restrict__ q,
                              const float* __restrict__ k, float Uf) {
    int row = blockIdx.x * 8 + (threadIdx.x >> 5);
    int lane = threadIdx.x & 31;
    if (row >= BB * QQ) return;
    int b = row / QQ;

    const float* mp = g_Mpart + (size_t)row * NTILES;
    float gmax = -3.0e38f;
#pragma unroll
    for (int t = 0; t < NTILES; t++) gmax = fmaxf(gmax, mp[t]);
    float thr = gmax - WWIN;

    const float* qr = q + (size_t)row * DD;
    const float* ws = g_wsum + b * DD;
    float qw = 0.f;
#pragma unroll
    for (int t = 0; t < DD / 32; t++)
        qw += qr[t * 32 + lane] * ws[t * 32 + lane];
#pragma unroll
    for (int off = 16; off > 0; off >>= 1)
        qw += __shfl_xor_sync(0xffffffffu, qw, off);

    const float* kb = k + (size_t)b * KVN * DD;
    float best = -3.0e38f;
#pragma unroll 1
    for (int t = 0; t < NTILES; t++) {
        if (mp[t] < thr) continue;
        const uint32_t* cw = g_cand + ((size_t)row * NTILES + t) * 4;
#pragma unroll
        for (int w = 0; w < 4; w++) {
            uint32_t m = cw[w];
            while (m) {
                int bit = __ffs(m) - 1;
                m &= m - 1;
                int col = t * 128 + w * 32 + bit;
                const float* kr = kb + (size_t)col * DD;
                float d = 0.f;
#pragma unroll
                for (int tt = 0; tt < DD / 32; tt++)
                    d += qr[tt * 32 + lane] * kr[tt * 32 + lane];
#pragma unroll
                for (int off = 16; off > 0; off >>= 1)
                    d += __shfl_xor_sync(0xffffffffu, d, off);
                best = fmaxf(best, d);
            }
        }
    }
    if (lane == 0) g_M[row] = best - qw / Uf;
}

// ---------------- kernel 6: top-60 tournament ------------------------------------
__global__ void topk_kernel() {
    int b = blockIdx.x;
    __shared__ unsigned long long keys[QQ];
    __shared__ unsigned long long warpmax[32];
    __shared__ int s_owner;
    int tid = threadIdx.x;
    int lane = tid & 31, warp = tid >> 5;

#pragma unroll
    for (int rep = 0; rep < 2; rep++) {
        int i = rep * 1024 + tid;
        uint32_t u = __float_as_uint(g_M[b * QQ + i]);
        u = (u & 0x80000000u) ? ~u : (u | 0x80000000u);
        keys[i] = ((unsigned long long)u << 32) | (unsigned long long)(QQ - 1 - i);
    }
    __syncthreads();

    {
        unsigned long long m0 = keys[warp * 64 + lane];
        unsigned long long m1 = keys[warp * 64 + 32 + lane];
        unsigned long long m = (m0 > m1) ? m0 : m1;
#pragma unroll
        for (int off = 16; off > 0; off >>= 1) {
            unsigned long long o = __shfl_xor_sync(0xffffffffu, m, off);
            m = (o > m) ? o : m;
        }
        if (lane == 0) warpmax[warp] = m;
    }
    __syncthreads();

    for (int it = 0; it < UQ; it++) {
        if (warp == 0) {
            unsigned long long m = warpmax[lane];
#pragma unroll
            for (int off = 16; off > 0; off >>= 1) {
                unsigned long long o = __shfl_xor_sync(0xffffffffu, m, off);
                m = (o > m) ? o : m;
            }
            if (lane == 0) {
                int i = QQ - 1 - (int)(m & 0xFFFFFFFFull);
                g_topidx[b * UQ + it] = i;
                keys[i] = 0ull;
                s_owner = i >> 6;
            }
        }
        __syncthreads();
        int ow = s_owner;
        if (warp == ow) {
            unsigned long long m0 = keys[ow * 64 + lane];
            unsigned long long m1 = keys[ow * 64 + 32 + lane];
            unsigned long long m = (m0 > m1) ? m0 : m1;
#pragma unroll
            for (int off = 16; off > 0; off >>= 1) {
                unsigned long long o = __shfl_xor_sync(0xffffffffu, m, off);
                m = (o > m) ? o : m;
            }
            if (lane == 0) warpmax[ow] = m;
        }
        __syncthreads();
    }
}

// ---------------- kernel 7: fill output with v-mean ------------------------------
__global__ void fill_kernel(float* __restrict__ out) {
    size_t f = (size_t)blockIdx.x * 256 + threadIdx.x;
    int d4 = (int)(f & (DD / 4 - 1));
    size_t row = f >> 7;
    int b = (int)(row >> 11);
    float4 val = *(const float4*)(g_vmean + b * DD + d4 * 4);
    ((float4*)out)[f] = val;
}

// ---------------- kernel 8: logits S1 = q_bar @ k^T * scale ----------------------
__global__ void __launch_bounds__(256)
logits_kernel(const float* __restrict__ q, const float* __restrict__ k) {
    int b = blockIdx.y;
    int n0 = blockIdx.x * 64;
    __shared__ int   tix[UQ];
    __shared__ float qs2[16][64];
    __shared__ float ks2[16][64];
    int tid = threadIdx.x;
    if (tid < UQ) tix[tid] = g_topidx[b * UQ + tid];

    int tx = tid & 15, ty = tid >> 4;
    float acc[4][4];
#pragma unroll
    for (int i = 0; i < 4; i++)
#pragma unroll
        for (int j = 0; j < 4; j++) acc[i][j] = 0.f;

    const float* qb = q + (size_t)b * QQ * DD;
    const float* kb = k + (size_t)b * KVN * DD;

    for (int dt = 0; dt < DD; dt += 16) {
        __syncthreads();
        if (tid < 240) {
            int i = tid >> 2, hh = (tid & 3) * 4;
            float4 v4 = *(const float4*)(qb + (size_t)tix[i] * DD + dt + hh);
            qs2[hh + 0][i] = v4.x; qs2[hh + 1][i] = v4.y;
            qs2[hh + 2][i] = v4.z; qs2[hh + 3][i] = v4.w;
        }
        {
            int r2 = tid >> 2, h2 = (tid & 3) * 4;
            float4 a4 = *(const float4*)(kb + (size_t)(n0 + r2) * DD + dt + h2);
            ks2[h2 + 0][r2] = a4.x; ks2[h2 + 1][r2] = a4.y;
            ks2[h2 + 2][r2] = a4.z; ks2[h2 + 3][r2] = a4.w;
        }
        __syncthreads();
#pragma unroll
        for (int kk = 0; kk < 16; kk++) {
            float a[4], bb[4];
            *(float4*)&a[0]  = *(float4*)&qs2[kk][ty * 4];
            *(float4*)&bb[0] = *(float4*)&ks2[kk][tx * 4];
#pragma unroll
            for (int i = 0; i < 4; i++)
#pragma unroll
                for (int j = 0; j < 4; j++)
                    acc[i][j] += a[i] * bb[j];
        }
    }
    float scale = rsqrtf((float)KVN);
#pragma unroll
    for (int ii = 0; ii < 4; ii++) {
        int i = ty * 4 + ii;
        if (i < UQ) {
#pragma unroll
            for (int j = 0; j < 4; j++)
                g_S1[((size_t)b * UQ + i) * KVN + n0 + tx * 4 + j] =
                    acc[ii][j] * scale;
        }
    }
}

// ---------------- kernel 9: row softmax ------------------------------------------
__global__ void softmax_kernel() {
    int row = blockIdx.x;
    float* p = g_S1 + (size_t)row * KVN;
    __shared__ float sred[256];
    int tid = threadIdx.x;

    float m = -3.4e38f;
    for (int i = tid; i < KVN; i += 256) m = fmaxf(m, p[i]);
    sred[tid] = m; __syncthreads();
    for (int s = 128; s > 0; s >>= 1) {
        if (tid < s) sred[tid] = fmaxf(sred[tid], sred[tid + s]);
        __syncthreads();
    }
    m = sred[0];
    __syncthreads();

    float sum = 0.f;
    for (int i = tid; i < KVN; i += 256) {
        float e = expf(p[i] - m);
        p[i] = e;
        sum += e;
    }
    sred[tid] = sum; __syncthreads();
    for (int s = 128; s > 0; s >>= 1) {
        if (tid < s) sred[tid] += sred[tid + s];
        __syncthreads();
    }
    float inv = 1.0f / sred[0];
    for (int i = tid; i < KVN; i += 256) p[i] *= inv;
}

// ---------------- kernel 10: O partials = P @ V (split kv) -----------------------
__global__ void __launch_bounds__(256)
pv_kernel(const float* __restrict__ v) {
    int b = blockIdx.z;
    int s = blockIdx.y;
    int d0 = blockIdx.x * 128;
    int kv0 = s * (KVN / PVS);     // 64

    __shared__ float ps[16][64];
    __shared__ float vs[16][128];
    int tid = threadIdx.x;
    int tx = tid & 15, ty = tid >> 4;
    float acc[4][8];
#pragma unroll
    for (int i = 0; i < 4; i++)
#pragma unroll
        for (int j = 0; j < 8; j++) acc[i][j] = 0.f;

    const float* vb = v + (size_t)b * KVN * DD;

    for (int kt = 0; kt < KVN / PVS; kt += 16) {
        __syncthreads();
        if (tid < 240) {
            int i = tid >> 2, hh = (tid & 3) * 4;
            float4 a4 = *(const float4*)(g_S1 + ((size_t)b * UQ + i) * KVN
                                         + kv0 + kt + hh);
            ps[hh + 0][i] = a4.x; ps[hh + 1][i] = a4.y;
            ps[hh + 2][i] = a4.z; ps[hh + 3][i] = a4.w;
        }
        {
            int kkr = tid >> 4, dc = (tid & 15) * 8;
            float4 a4 = *(const float4*)(vb + (size_t)(kv0 + kt + kkr) * DD + d0 + dc);
            float4 b4 = *(const float4*)(vb + (size_t)(kv0 + kt + kkr) * DD + d0 + dc + 4);
            vs[kkr][dc + 0] = a4.x; vs[kkr][dc + 1] = a4.y;
            vs[kkr][dc + 2] = a4.z; vs[kkr][dc + 3] = a4.w;
            vs[kkr][dc + 4] = b4.x; vs[kkr][dc + 5] = b4.y;
            vs[kkr][dc + 6] = b4.z; vs[kkr][dc + 7] = b4.w;
        }
        __syncthreads();
#pragma unroll
        for (int kk = 0; kk < 16; kk++) {
            float a[4], bb[8];
            *(float4*)&a[0]  = *(float4*)&ps[kk][ty * 4];
            *(float4*)&bb[0] = *(float4*)&vs[kk][tx * 8];
            *(float4*)&bb[4] = *(float4*)&vs[kk][tx * 8 + 4];
#pragma unroll
            for (int i = 0; i < 4; i++)
#pragma unroll
                for (int j = 0; j < 8; j++)
                    acc[i][j] += a[i] * bb[j];
        }
    }
#pragma unroll
    for (int ii = 0; ii < 4; ii++) {
        int i = ty * 4 + ii;
        if (i < UQ) {
#pragma unroll
            for (int j = 0; j < 8; j++)
                g_Opart[(((size_t)s * BB + b) * UQ + i) * DD + d0 + tx * 8 + j] =
                    acc[ii][j];
        }
    }
}

// ---------------- kernel 11: reduce PV partials + scatter ------------------------
__global__ void oreduce_kernel(float* __restrict__ out) {
    int idx = blockIdx.x * 256 + threadIdx.x;
    if (idx >= BB * UQ * DD) return;
    int d = idx % DD;
    int rest = idx / DD;
    int i = rest % UQ;
    int b = rest / UQ;
    float s = 0.f;
#pragma unroll
    for (int p = 0; p < PVS; p++)
        s += g_Opart[(((size_t)p * BB + b) * UQ + i) * DD + d];
    int row = g_topidx[b * UQ + i];
    out[((size_t)b * QQ + row) * DD + d] = s;
}

// ---------------- launch ----------------------------------------------------------
extern "C" void kernel_launch(void* const* d_in, const int* in_sizes, int n_in,
                              void* d_out, int out_size) {
    const float* q    = (const float*)d_in[0];
    const float* k    = (const float*)d_in[1];
    const float* v    = (const float*)d_in[2];
    const int*   sidx = (const int*)d_in[3];
    float* out = (float*)d_out;
    int U = in_sizes[3] / BB;

    split_kernel<<<(BB * QQ * DD / 4) / 256, 256>>>(q, k);
    zero_count_kernel<<<(BB * KVN + 255) / 256, 256>>>();
    count_kernel<<<(BB * U + 255) / 256, 256>>>(sidx, U);
    wsum_part_kernel<<<dim3(WS_SPLIT, BB), 128>>>(k, v);
    qkmax_tc_kernel<<<dim3(QQ / 128, KVN / 128, BB), 256>>>();
    wsum_reduce_kernel<<<8, 64>>>();
    refine_kernel<<<(BB * QQ) / 8, 256>>>(q, k, (float)U);
    topk_kernel<<<BB, 1024>>>();
    fill_kernel<<<(BB * QQ * DD / 4) / 256, 256>>>(out);
    logits_kernel<<<dim3(KVN / 64, BB), 256>>>(q, k);
    softmax_kernel<<<BB * UQ, 256>>>();
    pv_kernel<<<dim3(DD / 128, PVS, BB), 256>>>(v);
    oreduce_kernel<<<(BB * UQ * DD + 255) / 256, 256>>>(out);
}

// round 14
// speedup vs baseline: 1.0040x; 1.0040x over previous
#include <cuda_runtime.h>
#include <cuda_bf16.h>
#include <math.h>
#include <stdint.h>

// Problem constants
#define BB    4
#define QQ    2048
#define KVN   2048
#define DD    512
#define UQ    60
#define NTILES (KVN / 128)       // 16
#define WS_SPLIT 128
#define KVC   (KVN / WS_SPLIT)   // 16
#define PVS   32
#define CHUNK 32
#define NSTAGE (DD / CHUNK)      // 16
#define WWIN  1.0f               // rescue window (6-sigma bf16 dot err ~0.4)

// ---------------- scratch ----------------------------------------------------
__device__ int   g_count[BB * KVN];
__device__ float g_wspart[WS_SPLIT * BB * DD];
__device__ float g_vmpart[WS_SPLIT * BB * DD];
__device__ float g_wsum[BB * DD];
__device__ float g_vmean[BB * DD];
__device__ float g_M[BB * QQ];
__device__ float g_Mpart[BB * QQ * NTILES];
__device__ uint32_t g_cand[(size_t)BB * QQ * NTILES * 4];
__device__ int   g_topidx[BB * UQ];
__device__ float g_S1[(size_t)BB * UQ * KVN];
__device__ float g_Opart[(size_t)PVS * BB * UQ * DD];
__device__ __nv_bfloat16 g_qhi[(size_t)BB * QQ * DD];
__device__ __nv_bfloat16 g_khi[(size_t)BB * KVN * DD];

// ---------------- PTX helpers -------------------------------------------------
__device__ __forceinline__ uint32_t smem_u32(const void* p) {
    return (uint32_t)__cvta_generic_to_shared(p);
}
__device__ __forceinline__ void cpa16(uint32_t saddr, const void* g) {
    asm volatile("cp.async.cg.shared.global [%0], [%1], 16;" :: "r"(saddr), "l"(g));
}
__device__ __forceinline__ void ldsm4(uint32_t& r0, uint32_t& r1, uint32_t& r2,
                                      uint32_t& r3, uint32_t addr) {
    asm volatile("ldmatrix.sync.aligned.m8n8.x4.shared.b16 {%0,%1,%2,%3}, [%4];"
                 : "=r"(r0), "=r"(r1), "=r"(r2), "=r"(r3) : "r"(addr));
}
__device__ __forceinline__ void mma16816(float* c, const uint32_t* a,
                                         uint32_t b0, uint32_t b1) {
    asm volatile(
        "mma.sync.aligned.m16n8k16.row.col.f32.bf16.bf16.f32 "
        "{%0,%1,%2,%3}, {%4,%5,%6,%7}, {%8,%9}, {%0,%1,%2,%3};"
        : "+f"(c[0]), "+f"(c[1]), "+f"(c[2]), "+f"(c[3])
        : "r"(a[0]), "r"(a[1]), "r"(a[2]), "r"(a[3]), "r"(b0), "r"(b1));
}

// ---------------- kernel 0: bf16 hi of q and k ---------------------------------
__global__ void split_kernel(const float* __restrict__ q, const float* __restrict__ k) {
    size_t i = (size_t)blockIdx.x * 256 + threadIdx.x;   // float4 index
    float4 a = ((const float4*)q)[i];
    __nv_bfloat162 h01, h23;
    h01.x = __float2bfloat16(a.x); h01.y = __float2bfloat16(a.y);
    h23.x = __float2bfloat16(a.z); h23.y = __float2bfloat16(a.w);
    ((__nv_bfloat162*)g_qhi)[i * 2] = h01; ((__nv_bfloat162*)g_qhi)[i * 2 + 1] = h23;

    float4 bvec = ((const float4*)k)[i];
    h01.x = __float2bfloat16(bvec.x); h01.y = __float2bfloat16(bvec.y);
    h23.x = __float2bfloat16(bvec.z); h23.y = __float2bfloat16(bvec.w);
    ((__nv_bfloat162*)g_khi)[i * 2] = h01; ((__nv_bfloat162*)g_khi)[i * 2 + 1] = h23;
}

// ---------------- kernels 1,2: counts -----------------------------------------
__global__ void zero_count_kernel() {
    int i = blockIdx.x * blockDim.x + threadIdx.x;
    if (i < BB * KVN) g_count[i] = 0;
}
__global__ void count_kernel(const int* __restrict__ sidx, int U) {
    int i = blockIdx.x * blockDim.x + threadIdx.x;
    if (i < BB * U) {
        int b = i / U;
        atomicAdd(&g_count[b * KVN + sidx[i]], 1);
    }
}

// ---------------- kernel 3: weighted key sum + v mean (float4, 512 blocks) -----
// grid (WS_SPLIT=128, BB), block 128: thread t owns float4 column t; 16 kv rows.
__global__ void wsum_part_kernel(const float* __restrict__ k,
                                 const float* __restrict__ v) {
    int s = blockIdx.x;
    int b = blockIdx.y;
    int d4 = threadIdx.x;          // float4 index 0..127

    __shared__ float cntf[KVC];
    if (threadIdx.x < KVC)
        cntf[threadIdx.x] = (float)g_count[b * KVN + s * KVC + threadIdx.x];
    __syncthreads();

    const float4* kp = (const float4*)(k + ((size_t)b * KVN + (size_t)s * KVC) * DD) + d4;
    const float4* vp = (const float4*)(v + ((size_t)b * KVN + (size_t)s * KVC) * DD) + d4;
    float4 ws = make_float4(0.f, 0.f, 0.f, 0.f);
    float4 vm = make_float4(0.f, 0.f, 0.f, 0.f);
#pragma unroll
    for (int j = 0; j < KVC; j++) {
        float c = cntf[j];
        float4 kv = kp[(size_t)j * (DD / 4)];
        float4 vv = vp[(size_t)j * (DD / 4)];
        ws.x += c * kv.x; ws.y += c * kv.y; ws.z += c * kv.z; ws.w += c * kv.w;
        vm.x += vv.x;     vm.y += vv.y;     vm.z += vv.z;     vm.w += vv.w;
    }
    ((float4*)g_wspart)[((size_t)s * BB + b) * (DD / 4) + d4] = ws;
    ((float4*)g_vmpart)[((size_t)s * BB + b) * (DD / 4) + d4] = vm;
}

// float4 over d: 8 blocks x 64 threads cover BB*DD/4 vectors
__global__ void wsum_reduce_kernel() {
    int idx = blockIdx.x * 64 + threadIdx.x;   // 0..511
    if (idx >= BB * DD / 4) return;
    float4 ws = make_float4(0.f, 0.f, 0.f, 0.f);
    float4 vm = make_float4(0.f, 0.f, 0.f, 0.f);
#pragma unroll 8
    for (int s = 0; s < WS_SPLIT; s++) {
        float4 a = ((const float4*)g_wspart)[(size_t)s * (BB * DD / 4) + idx];
        float4 c = ((const float4*)g_vmpart)[(size_t)s * (BB * DD / 4) + idx];
        ws.x += a.x; ws.y += a.y; ws.z += a.z; ws.w += a.w;
        vm.x += c.x; vm.y += c.y; vm.z += c.z; vm.w += c.w;
    }
    ((float4*)g_wsum)[idx] = ws;
    vm.x *= (1.0f / KVN); vm.y *= (1.0f / KVN);
    vm.z *= (1.0f / KVN); vm.w *= (1.0f / KVN);
    ((float4*)g_vmean)[idx] = vm;
}

// ---------------- kernel 4: approx QK^T (bf16 HMMA) -> rowmax + cand bits ------
__global__ void __launch_bounds__(256, 2)
qkmax_tc_kernel() {
    __shared__ __nv_bfloat16 sA[3][128][40];
    __shared__ __nv_bfloat16 sB[3][128][40];
    __shared__ int      cmask[128];
    __shared__ float    smax[128][4];
    __shared__ float    rmax[128];
    __shared__ uint32_t bits[128][4];

    const int tid = threadIdx.x, lane = tid & 31, warp = tid >> 5;
    const int wm = warp >> 2, wn = warp & 3;
    const int b = blockIdx.z;
    const int m0 = blockIdx.x * 128, n0 = blockIdx.y * 128;

    const __nv_bfloat16* qh = g_qhi + (size_t)b * QQ * DD;
    const __nv_bfloat16* kh = g_khi + (size_t)b * KVN * DD;

    if (tid < 128) {
        cmask[tid] = g_count[b * KVN + n0 + tid];
        bits[tid][0] = 0u; bits[tid][1] = 0u; bits[tid][2] = 0u; bits[tid][3] = 0u;
    }

    const int lrow = tid >> 1, lhalf = tid & 1;
    const size_t gaoff = (size_t)(m0 + lrow) * DD + lhalf * 8;
    const size_t gboff = (size_t)(n0 + lrow) * DD + lhalf * 8;
    const uint32_t saA = smem_u32(&sA[0][lrow][lhalf * 8]);
    const uint32_t saB = smem_u32(&sB[0][lrow][lhalf * 8]);
    const uint32_t BUFSTRIDE = 128 * 40 * 2;

    const int lr = lane & 15;
    const int lc8 = (lane >> 4) * 8;
    const uint32_t aAh = smem_u32(&sA[0][wm * 64 + lr][lc8]);
    const uint32_t aBh = smem_u32(&sB[0][wn * 32 + lr][lc8]);

    float acc[4][4][4];
#pragma unroll
    for (int mt = 0; mt < 4; mt++)
#pragma unroll
        for (int nt = 0; nt < 4; nt++)
#pragma unroll
            for (int r = 0; r < 4; r++) acc[mt][nt][r] = 0.f;

    auto issue = [&](int ks) {
        uint32_t bo = (uint32_t)(ks % 3) * BUFSTRIDE;
        int dt = ks * CHUNK;
        cpa16(saA + bo,      qh + gaoff + dt);
        cpa16(saA + bo + 32, qh + gaoff + dt + 16);
        cpa16(saB + bo,      kh + gboff + dt);
        cpa16(saB + bo + 32, kh + gboff + dt + 16);
        asm volatile("cp.async.commit_group;");
    };

    issue(0);
    issue(1);
#pragma unroll 1
    for (int ks = 0; ks < NSTAGE; ks++) {
        if (ks < NSTAGE - 1)
            asm volatile("cp.async.wait_group 1;");
        else
            asm volatile("cp.async.wait_group 0;");
        __syncthreads();
        if (ks + 2 < NSTAGE) issue(ks + 2);

        uint32_t bo = (uint32_t)(ks % 3) * BUFSTRIDE;
#pragma unroll
        for (int kh2 = 0; kh2 < 2; kh2++) {
            uint32_t ko = bo + kh2 * 32;
            uint32_t a[4][4], bf[2][4];
#pragma unroll
            for (int mt = 0; mt < 4; mt++)
                ldsm4(a[mt][0], a[mt][1], a[mt][2], a[mt][3], aAh + ko + mt * 1280);
#pragma unroll
            for (int nc = 0; nc < 2; nc++)
                ldsm4(bf[nc][0], bf[nc][1], bf[nc][2], bf[nc][3], aBh + ko + nc * 1280);
#pragma unroll
            for (int mt = 0; mt < 4; mt++)
#pragma unroll
                for (int nt = 0; nt < 4; nt++) {
                    int nc = nt >> 1, s = nt & 1;
                    mma16816(acc[mt][nt], a[mt], bf[nc][s], bf[nc][2 + s]);
                }
        }
    }

#pragma unroll
    for (int nt = 0; nt < 4; nt++) {
        int c = wn * 32 + nt * 8 + (lane & 3) * 2;
        bool ok0 = cmask[c] > 0, ok1 = cmask[c + 1] > 0;
#pragma unroll
        for (int mt = 0; mt < 4; mt++) {
            if (!ok0) { acc[mt][nt][0] = -3.0e38f; acc[mt][nt][2] = -3.0e38f; }
            if (!ok1) { acc[mt][nt][1] = -3.0e38f; acc[mt][nt][3] = -3.0e38f; }
        }
    }
    float rm[8];
#pragma unroll
    for (int i = 0; i < 8; i++) rm[i] = -3.0e38f;
#pragma unroll
    for (int nt = 0; nt < 4; nt++)
#pragma unroll
        for (int mt = 0; mt < 4; mt++) {
            rm[mt * 2]     = fmaxf(rm[mt * 2],     fmaxf(acc[mt][nt][0], acc[mt][nt][1]));
            rm[mt * 2 + 1] = fmaxf(rm[mt * 2 + 1], fmaxf(acc[mt][nt][2], acc[mt][nt][3]));
        }
#pragma unroll
    for (int i = 0; i < 8; i++) {
        rm[i] = fmaxf(rm[i], __shfl_xor_sync(0xffffffffu, rm[i], 1));
        rm[i] = fmaxf(rm[i], __shfl_xor_sync(0xffffffffu, rm[i], 2));
    }
    if ((lane & 3) == 0) {
        int g = lane >> 2;
#pragma unroll
        for (int mt = 0; mt < 4; mt++) {
            smax[wm * 64 + mt * 16 + g][wn]     = rm[mt * 2];
            smax[wm * 64 + mt * 16 + g + 8][wn] = rm[mt * 2 + 1];
        }
    }
    __syncthreads();
    if (tid < 128)
        rmax[tid] = fmaxf(fmaxf(smax[tid][0], smax[tid][1]),
                          fmaxf(smax[tid][2], smax[tid][3]));
    __syncthreads();

    {
        int g = lane >> 2;
#pragma unroll
        for (int mt = 0; mt < 4; mt++) {
            int r0 = wm * 64 + mt * 16 + g;
            float t0 = rmax[r0] - WWIN, t1 = rmax[r0 + 8] - WWIN;
#pragma unroll
            for (int nt = 0; nt < 4; nt++) {
                int c = wn * 32 + nt * 8 + (lane & 3) * 2;
                if (acc[mt][nt][0] >= t0) atomicOr(&bits[r0][c >> 5], 1u << (c & 31));
                if (acc[mt][nt][1] >= t0) atomicOr(&bits[r0][(c + 1) >> 5], 1u << ((c + 1) & 31));
                if (acc[mt][nt][2] >= t1) atomicOr(&bits[r0 + 8][c >> 5], 1u << (c & 31));
                if (acc[mt][nt][3] >= t1) atomicOr(&bits[r0 + 8][(c + 1) >> 5], 1u << ((c + 1) & 31));
            }
        }
    }
    __syncthreads();
    if (tid < 128) {
        size_t ro = ((size_t)b * QQ + m0 + tid) * NTILES + blockIdx.y;
        g_Mpart[ro] = rmax[tid];
        *(uint4*)&g_cand[ro * 4] = *(uint4*)&bits[tid][0];
    }
}

// ---------------- kernel 5: refine — exact max + M -----------------------------
__global__ void refine_kernel(const float* __restrict__ q,
                              const float* __restrict__ k, float Uf) {
    int row = blockIdx.x * 8 + (threadIdx.x >> 5);
    int lane = threadIdx.x & 31;
    if (row >= BB * QQ) return;
    int b = row / QQ;

    const float* mp = g_Mpart + (size_t)row * NTILES;
    float gmax = -3.0e38f;
#pragma unroll
    for (int t = 0; t < NTILES; t++) gmax = fmaxf(gmax, mp[t]);
    float thr = gmax - WWIN;

    const float* qr = q + (size_t)row * DD;
    const float* ws = g_wsum + b * DD;
    float qw = 0.f;
#pragma unroll
    for (int t = 0; t < DD / 32; t++)
        qw += qr[t * 32 + lane] * ws[t * 32 + lane];
#pragma unroll
    for (int off = 16; off > 0; off >>= 1)
        qw += __shfl_xor_sync(0xffffffffu, qw, off);

    const float* kb = k + (size_t)b * KVN * DD;
    float best = -3.0e38f;
#pragma unroll 1
    for (int t = 0; t < NTILES; t++) {
        if (mp[t] < thr) continue;
        const uint32_t* cw = g_cand + ((size_t)row * NTILES + t) * 4;
#pragma unroll
        for (int w = 0; w < 4; w++) {
            uint32_t m = cw[w];
            while (m) {
                int bit = __ffs(m) - 1;
                m &= m - 1;
                int col = t * 128 + w * 32 + bit;
                const float* kr = kb + (size_t)col * DD;
                float d = 0.f;
#pragma unroll
                for (int tt = 0; tt < DD / 32; tt++)
                    d += qr[tt * 32 + lane] * kr[tt * 32 + lane];
#pragma unroll
                for (int off = 16; off > 0; off >>= 1)
                    d += __shfl_xor_sync(0xffffffffu, d, off);
                best = fmaxf(best, d);
            }
        }
    }
    if (lane == 0) g_M[row] = best - qw / Uf;
}

// ---------------- kernel 6: top-60 tournament ------------------------------------
__global__ void topk_kernel() {
    int b = blockIdx.x;
    __shared__ unsigned long long keys[QQ];
    __shared__ unsigned long long warpmax[32];
    __shared__ int s_owner;
    int tid = threadIdx.x;
    int lane = tid & 31, warp = tid >> 5;

#pragma unroll
    for (int rep = 0; rep < 2; rep++) {
        int i = rep * 1024 + tid;
        uint32_t u = __float_as_uint(g_M[b * QQ + i]);
        u = (u & 0x80000000u) ? ~u : (u | 0x80000000u);
        keys[i] = ((unsigned long long)u << 32) | (unsigned long long)(QQ - 1 - i);
    }
    __syncthreads();

    {
        unsigned long long m0 = keys[warp * 64 + lane];
        unsigned long long m1 = keys[warp * 64 + 32 + lane];
        unsigned long long m = (m0 > m1) ? m0 : m1;
#pragma unroll
        for (int off = 16; off > 0; off >>= 1) {
            unsigned long long o = __shfl_xor_sync(0xffffffffu, m, off);
            m = (o > m) ? o : m;
        }
        if (lane == 0) warpmax[warp] = m;
    }
    __syncthreads();

    for (int it = 0; it < UQ; it++) {
        if (warp == 0) {
            unsigned long long m = warpmax[lane];
#pragma unroll
            for (int off = 16; off > 0; off >>= 1) {
                unsigned long long o = __shfl_xor_sync(0xffffffffu, m, off);
                m = (o > m) ? o : m;
            }
            if (lane == 0) {
                int i = QQ - 1 - (int)(m & 0xFFFFFFFFull);
                g_topidx[b * UQ + it] = i;
                keys[i] = 0ull;
                s_owner = i >> 6;
            }
        }
        __syncthreads();
        int ow = s_owner;
        if (warp == ow) {
            unsigned long long m0 = keys[ow * 64 + lane];
            unsigned long long m1 = keys[ow * 64 + 32 + lane];
            unsigned long long m = (m0 > m1) ? m0 : m1;
#pragma unroll
            for (int off = 16; off > 0; off >>= 1) {
                unsigned long long o = __shfl_xor_sync(0xffffffffu, m, off);
                m = (o > m) ? o : m;
            }
            if (lane == 0) warpmax[ow] = m;
        }
        __syncthreads();
    }
}

// ---------------- kernel 7: fill output with v-mean ------------------------------
__global__ void fill_kernel(float* __restrict__ out) {
    size_t f = (size_t)blockIdx.x * 256 + threadIdx.x;
    int d4 = (int)(f & (DD / 4 - 1));
    size_t row = f >> 7;
    int b = (int)(row >> 11);
    float4 val = *(const float4*)(g_vmean + b * DD + d4 * 4);
    ((float4*)out)[f] = val;
}

// ---------------- kernel 8: logits S1 = q_bar @ k^T * scale ----------------------
__global__ void __launch_bounds__(256)
logits_kernel(const float* __restrict__ q, const float* __restrict__ k) {
    int b = blockIdx.y;
    int n0 = blockIdx.x * 64;
    __shared__ int   tix[UQ];
    __shared__ float qs2[16][64];
    __shared__ float ks2[16][64];
    int tid = threadIdx.x;
    if (tid < UQ) tix[tid] = g_topidx[b * UQ + tid];

    int tx = tid & 15, ty = tid >> 4;
    float acc[4][4];
#pragma unroll
    for (int i = 0; i < 4; i++)
#pragma unroll
        for (int j = 0; j < 4; j++) acc[i][j] = 0.f;

    const float* qb = q + (size_t)b * QQ * DD;
    const float* kb = k + (size_t)b * KVN * DD;

    for (int dt = 0; dt < DD; dt += 16) {
        __syncthreads();
        if (tid < 240) {
            int i = tid >> 2, hh = (tid & 3) * 4;
            float4 v4 = *(const float4*)(qb + (size_t)tix[i] * DD + dt + hh);
            qs2[hh + 0][i] = v4.x; qs2[hh + 1][i] = v4.y;
            qs2[hh + 2][i] = v4.z; qs2[hh + 3][i] = v4.w;
        }
        {
            int r2 = tid >> 2, h2 = (tid & 3) * 4;
            float4 a4 = *(const float4*)(kb + (size_t)(n0 + r2) * DD + dt + h2);
            ks2[h2 + 0][r2] = a4.x; ks2[h2 + 1][r2] = a4.y;
            ks2[h2 + 2][r2] = a4.z; ks2[h2 + 3][r2] = a4.w;
        }
        __syncthreads();
#pragma unroll
        for (int kk = 0; kk < 16; kk++) {
            float a[4], bb[4];
            *(float4*)&a[0]  = *(float4*)&qs2[kk][ty * 4];
            *(float4*)&bb[0] = *(float4*)&ks2[kk][tx * 4];
#pragma unroll
            for (int i = 0; i < 4; i++)
#pragma unroll
                for (int j = 0; j < 4; j++)
                    acc[i][j] += a[i] * bb[j];
        }
    }
    float scale = rsqrtf((float)KVN);
#pragma unroll
    for (int ii = 0; ii < 4; ii++) {
        int i = ty * 4 + ii;
        if (i < UQ) {
#pragma unroll
            for (int j = 0; j < 4; j++)
                g_S1[((size_t)b * UQ + i) * KVN + n0 + tx * 4 + j] =
                    acc[ii][j] * scale;
        }
    }
}

// ---------------- kernel 9: row softmax ------------------------------------------
__global__ void softmax_kernel() {
    int row = blockIdx.x;
    float* p = g_S1 + (size_t)row * KVN;
    __shared__ float sred[256];
    int tid = threadIdx.x;

    float m = -3.4e38f;
    for (int i = tid; i < KVN; i += 256) m = fmaxf(m, p[i]);
    sred[tid] = m; __syncthreads();
    for (int s = 128; s > 0; s >>= 1) {
        if (tid < s) sred[tid] = fmaxf(sred[tid], sred[tid + s]);
        __syncthreads();
    }
    m = sred[0];
    __syncthreads();

    float sum = 0.f;
    for (int i = tid; i < KVN; i += 256) {
        float e = expf(p[i] - m);
        p[i] = e;
        sum += e;
    }
    sred[tid] = sum; __syncthreads();
    for (int s = 128; s > 0; s >>= 1) {
        if (tid < s) sred[tid] += sred[tid + s];
        __syncthreads();
    }
    float inv = 1.0f / sred[0];
    for (int i = tid; i < KVN; i += 256) p[i] *= inv;
}

// ---------------- kernel 10: O partials = P @ V (split kv) -----------------------
__global__ void __launch_bounds__(256)
pv_kernel(const float* __restrict__ v) {
    int b = blockIdx.z;
    int s = blockIdx.y;
    int d0 = blockIdx.x * 128;
    int kv0 = s * (KVN / PVS);     // 64

    __shared__ float ps[16][64];
    __shared__ float vs[16][128];
    int tid = threadIdx.x;
    int tx = tid & 15, ty = tid >> 4;
    float acc[4][8];
#pragma unroll
    for (int i = 0; i < 4; i++)
#pragma unroll
        for (int j = 0; j < 8; j++) acc[i][j] = 0.f;

    const float* vb = v + (size_t)b * KVN * DD;

    for (int kt = 0; kt < KVN / PVS; kt += 16) {
        __syncthreads();
        if (tid < 240) {
            int i = tid >> 2, hh = (tid & 3) * 4;
            float4 a4 = *(const float4*)(g_S1 + ((size_t)b * UQ + i) * KVN
                                         + kv0 + kt + hh);
            ps[hh + 0][i] = a4.x; ps[hh + 1][i] = a4.y;
            ps[hh + 2][i] = a4.z; ps[hh + 3][i] = a4.w;
        }
        {
            int kkr = tid >> 4, dc = (tid & 15) * 8;
            float4 a4 = *(const float4*)(vb + (size_t)(kv0 + kt + kkr) * DD + d0 + dc);
            float4 b4 = *(const float4*)(vb + (size_t)(kv0 + kt + kkr) * DD + d0 + dc + 4);
            vs[kkr][dc + 0] = a4.x; vs[kkr][dc + 1] = a4.y;
            vs[kkr][dc + 2] = a4.z; vs[kkr][dc + 3] = a4.w;
            vs[kkr][dc + 4] = b4.x; vs[kkr][dc + 5] = b4.y;
            vs[kkr][dc + 6] = b4.z; vs[kkr][dc + 7] = b4.w;
        }
        __syncthreads();
#pragma unroll
        for (int kk = 0; kk < 16; kk++) {
            float a[4], bb[8];
            *(float4*)&a[0]  = *(float4*)&ps[kk][ty * 4];
            *(float4*)&bb[0] = *(float4*)&vs[kk][tx * 8];
            *(float4*)&bb[4] = *(float4*)&vs[kk][tx * 8 + 4];
#pragma unroll
            for (int i = 0; i < 4; i++)
#pragma unroll
                for (int j = 0; j < 8; j++)
                    acc[i][j] += a[i] * bb[j];
        }
    }
#pragma unroll
    for (int ii = 0; ii < 4; ii++) {
        int i = ty * 4 + ii;
        if (i < UQ) {
#pragma unroll
            for (int j = 0; j < 8; j++)
                g_Opart[(((size_t)s * BB + b) * UQ + i) * DD + d0 + tx * 8 + j] =
                    acc[ii][j];
        }
    }
}

// ---------------- kernel 11: reduce PV partials + scatter ------------------------
__global__ void oreduce_kernel(float* __restrict__ out) {
    int idx = blockIdx.x * 256 + threadIdx.x;
    if (idx >= BB * UQ * DD) return;
    int d = idx % DD;
    int rest = idx / DD;
    int i = rest % UQ;
    int b = rest / UQ;
    float s = 0.f;
#pragma unroll
    for (int p = 0; p < PVS; p++)
        s += g_Opart[(((size_t)p * BB + b) * UQ + i) * DD + d];
    int row = g_topidx[b * UQ + i];
    out[((size_t)b * QQ + row) * DD + d] = s;
}

// ---------------- launch ----------------------------------------------------------
extern "C" void kernel_launch(void* const* d_in, const int* in_sizes, int n_in,
                              void* d_out, int out_size) {
    const float* q    = (const float*)d_in[0];
    const float* k    = (const float*)d_in[1];
    const float* v    = (const float*)d_in[2];
    const int*   sidx = (const int*)d_in[3];
    float* out = (float*)d_out;
    int U = in_sizes[3] / BB;

    split_kernel<<<(BB * QQ * DD / 4) / 256, 256>>>(q, k);
    zero_count_kernel<<<(BB * KVN + 255) / 256, 256>>>();
    count_kernel<<<(BB * U + 255) / 256, 256>>>(sidx, U);
    wsum_part_kernel<<<dim3(WS_SPLIT, BB), 128>>>(k, v);
    qkmax_tc_kernel<<<dim3(QQ / 128, KVN / 128, BB), 256>>>();
    wsum_reduce_kernel<<<8, 64>>>();
    refine_kernel<<<(BB * QQ) / 8, 256>>>(q, k, (float)U);
    topk_kernel<<<BB, 1024>>>();
    fill_kernel<<<(BB * QQ * DD / 4) / 256, 256>>>(out);
    logits_kernel<<<dim3(KVN / 64, BB), 256>>>(q, k);
    softmax_kernel<<<BB * UQ, 256>>>();
    pv_kernel<<<dim3(DD / 128, PVS, BB), 256>>>(v);
    oreduce_kernel<<<(BB * UQ * DD + 255) / 256, 256>>>(out);
}

// round 15
// speedup vs baseline: 1.0646x; 1.0603x over previous
#include <cuda_runtime.h>
#include <cuda_bf16.h>
#include <math.h>
#include <stdint.h>

// Problem constants
#define BB    4
#define QQ    2048
#define KVN   2048
#define DD    512
#define UQ    60
#define NTILES (KVN / 128)       // 16
#define WS_SPLIT 32
#define KVC   (KVN / WS_SPLIT)   // 64
#define PVS   32
#define CHUNK 32
#define NSTAGE (DD / CHUNK)      // 16
#define WWIN  1.0f               // rescue window (6-sigma bf16 dot err ~0.4)

// ---------------- scratch ----------------------------------------------------
__device__ int   g_count[BB * KVN];
__device__ float g_wspart[WS_SPLIT * BB * DD];
__device__ float g_vmpart[WS_SPLIT * BB * DD];
__device__ float g_wsum[BB * DD];
__device__ float g_vmean[BB * DD];
__device__ float g_M[BB * QQ];
__device__ float g_Mpart[BB * QQ * NTILES];
__device__ uint32_t g_cand[(size_t)BB * QQ * NTILES * 4];
__device__ int   g_topidx[BB * UQ];
__device__ float g_S1[(size_t)BB * UQ * KVN];
__device__ float g_Opart[(size_t)PVS * BB * UQ * DD];
__device__ __nv_bfloat16 g_qhi[(size_t)BB * QQ * DD];
__device__ __nv_bfloat16 g_khi[(size_t)BB * KVN * DD];

// ---------------- PTX helpers -------------------------------------------------
__device__ __forceinline__ uint32_t smem_u32(const void* p) {
    return (uint32_t)__cvta_generic_to_shared(p);
}
__device__ __forceinline__ void cpa16(uint32_t saddr, const void* g) {
    asm volatile("cp.async.cg.shared.global [%0], [%1], 16;" :: "r"(saddr), "l"(g));
}
__device__ __forceinline__ void ldsm4(uint32_t& r0, uint32_t& r1, uint32_t& r2,
                                      uint32_t& r3, uint32_t addr) {
    asm volatile("ldmatrix.sync.aligned.m8n8.x4.shared.b16 {%0,%1,%2,%3}, [%4];"
                 : "=r"(r0), "=r"(r1), "=r"(r2), "=r"(r3) : "r"(addr));
}
__device__ __forceinline__ void mma16816(float* c, const uint32_t* a,
                                         uint32_t b0, uint32_t b1) {
    asm volatile(
        "mma.sync.aligned.m16n8k16.row.col.f32.bf16.bf16.f32 "
        "{%0,%1,%2,%3}, {%4,%5,%6,%7}, {%8,%9}, {%0,%1,%2,%3};"
        : "+f"(c[0]), "+f"(c[1]), "+f"(c[2]), "+f"(c[3])
        : "r"(a[0]), "r"(a[1]), "r"(a[2]), "r"(a[3]), "r"(b0), "r"(b1));
}

// ---------------- kernel 0: bf16 hi of q and k ---------------------------------
__global__ void split_kernel(const float* __restrict__ q, const float* __restrict__ k) {
    size_t i = (size_t)blockIdx.x * 256 + threadIdx.x;   // float4 index
    float4 a = ((const float4*)q)[i];
    __nv_bfloat162 h01, h23;
    h01.x = __float2bfloat16(a.x); h01.y = __float2bfloat16(a.y);
    h23.x = __float2bfloat16(a.z); h23.y = __float2bfloat16(a.w);
    ((__nv_bfloat162*)g_qhi)[i * 2] = h01; ((__nv_bfloat162*)g_qhi)[i * 2 + 1] = h23;

    float4 bvec = ((const float4*)k)[i];
    h01.x = __float2bfloat16(bvec.x); h01.y = __float2bfloat16(bvec.y);
    h23.x = __float2bfloat16(bvec.z); h23.y = __float2bfloat16(bvec.w);
    ((__nv_bfloat162*)g_khi)[i * 2] = h01; ((__nv_bfloat162*)g_khi)[i * 2 + 1] = h23;
}

// ---------------- kernels 1,2: counts -----------------------------------------
__global__ void zero_count_kernel() {
    int i = blockIdx.x * blockDim.x + threadIdx.x;
    if (i < BB * KVN) g_count[i] = 0;
}
__global__ void count_kernel(const int* __restrict__ sidx, int U) {
    int i = blockIdx.x * blockDim.x + threadIdx.x;
    if (i < BB * U) {
        int b = i / U;
        atomicAdd(&g_count[b * KVN + sidx[i]], 1);
    }
}

// ---------------- kernel 3: weighted key sum + v mean --------------------------
// grid (WS_SPLIT=32, BB), block 512: 128 float4-cols x 4 row-groups of 16 rows.
// 4-way smem reduce (fixed group order) -> one partial per slice.
__global__ void __launch_bounds__(512)
wsum_part_kernel(const float* __restrict__ k, const float* __restrict__ v) {
    int s = blockIdx.x;
    int b = blockIdx.y;
    int d4 = threadIdx.x & 127;    // float4 column 0..127
    int g  = threadIdx.x >> 7;     // row group 0..3

    __shared__ float  cntf[KVC];
    __shared__ float4 redw[4][128];
    __shared__ float4 redv[4][128];
    if (threadIdx.x < KVC)
        cntf[threadIdx.x] = (float)g_count[b * KVN + s * KVC + threadIdx.x];
    __syncthreads();

    const float4* kp = (const float4*)(k + ((size_t)b * KVN + (size_t)s * KVC) * DD) + d4;
    const float4* vp = (const float4*)(v + ((size_t)b * KVN + (size_t)s * KVC) * DD) + d4;
    float4 ws = make_float4(0.f, 0.f, 0.f, 0.f);
    float4 vm = make_float4(0.f, 0.f, 0.f, 0.f);
#pragma unroll
    for (int j = 0; j < 16; j++) {
        int row = g * 16 + j;
        float c = cntf[row];
        float4 kv = kp[(size_t)row * (DD / 4)];
        float4 vv = vp[(size_t)row * (DD / 4)];
        ws.x += c * kv.x; ws.y += c * kv.y; ws.z += c * kv.z; ws.w += c * kv.w;
        vm.x += vv.x;     vm.y += vv.y;     vm.z += vv.z;     vm.w += vv.w;
    }
    redw[g][d4] = ws;
    redv[g][d4] = vm;
    __syncthreads();
    if (g == 0) {
        float4 w0 = redw[0][d4], w1 = redw[1][d4], w2 = redw[2][d4], w3 = redw[3][d4];
        float4 v0 = redv[0][d4], v1 = redv[1][d4], v2 = redv[2][d4], v3 = redv[3][d4];
        float4 W, V;
        W.x = ((w0.x + w1.x) + w2.x) + w3.x;
        W.y = ((w0.y + w1.y) + w2.y) + w3.y;
        W.z = ((w0.z + w1.z) + w2.z) + w3.z;
        W.w = ((w0.w + w1.w) + w2.w) + w3.w;
        V.x = ((v0.x + v1.x) + v2.x) + v3.x;
        V.y = ((v0.y + v1.y) + v2.y) + v3.y;
        V.z = ((v0.z + v1.z) + v2.z) + v3.z;
        V.w = ((v0.w + v1.w) + v2.w) + v3.w;
        ((float4*)g_wspart)[((size_t)s * BB + b) * (DD / 4) + d4] = W;
        ((float4*)g_vmpart)[((size_t)s * BB + b) * (DD / 4) + d4] = V;
    }
}

// float4 over d: 8 blocks x 64 threads cover BB*DD/4 vectors (32 partials)
__global__ void wsum_reduce_kernel() {
    int idx = blockIdx.x * 64 + threadIdx.x;   // 0..511
    if (idx >= BB * DD / 4) return;
    float4 ws = make_float4(0.f, 0.f, 0.f, 0.f);
    float4 vm = make_float4(0.f, 0.f, 0.f, 0.f);
#pragma unroll
    for (int s = 0; s < WS_SPLIT; s++) {
        float4 a = ((const float4*)g_wspart)[(size_t)s * (BB * DD / 4) + idx];
        float4 c = ((const float4*)g_vmpart)[(size_t)s * (BB * DD / 4) + idx];
        ws.x += a.x; ws.y += a.y; ws.z += a.z; ws.w += a.w;
        vm.x += c.x; vm.y += c.y; vm.z += c.z; vm.w += c.w;
    }
    ((float4*)g_wsum)[idx] = ws;
    vm.x *= (1.0f / KVN); vm.y *= (1.0f / KVN);
    vm.z *= (1.0f / KVN); vm.w *= (1.0f / KVN);
    ((float4*)g_vmean)[idx] = vm;
}

// ---------------- kernel 4: approx QK^T (bf16 HMMA) -> rowmax + cand bits ------
__global__ void __launch_bounds__(256, 2)
qkmax_tc_kernel() {
    __shared__ __nv_bfloat16 sA[3][128][40];
    __shared__ __nv_bfloat16 sB[3][128][40];
    __shared__ int      cmask[128];
    __shared__ float    smax[128][4];
    __shared__ float    rmax[128];
    __shared__ uint32_t bits[128][4];

    const int tid = threadIdx.x, lane = tid & 31, warp = tid >> 5;
    const int wm = warp >> 2, wn = warp & 3;
    const int b = blockIdx.z;
    const int m0 = blockIdx.x * 128, n0 = blockIdx.y * 128;

    const __nv_bfloat16* qh = g_qhi + (size_t)b * QQ * DD;
    const __nv_bfloat16* kh = g_khi + (size_t)b * KVN * DD;

    if (tid < 128) {
        cmask[tid] = g_count[b * KVN + n0 + tid];
        bits[tid][0] = 0u; bits[tid][1] = 0u; bits[tid][2] = 0u; bits[tid][3] = 0u;
    }

    const int lrow = tid >> 1, lhalf = tid & 1;
    const size_t gaoff = (size_t)(m0 + lrow) * DD + lhalf * 8;
    const size_t gboff = (size_t)(n0 + lrow) * DD + lhalf * 8;
    const uint32_t saA = smem_u32(&sA[0][lrow][lhalf * 8]);
    const uint32_t saB = smem_u32(&sB[0][lrow][lhalf * 8]);
    const uint32_t BUFSTRIDE = 128 * 40 * 2;

    const int lr = lane & 15;
    const int lc8 = (lane >> 4) * 8;
    const uint32_t aAh = smem_u32(&sA[0][wm * 64 + lr][lc8]);
    const uint32_t aBh = smem_u32(&sB[0][wn * 32 + lr][lc8]);

    float acc[4][4][4];
#pragma unroll
    for (int mt = 0; mt < 4; mt++)
#pragma unroll
        for (int nt = 0; nt < 4; nt++)
#pragma unroll
            for (int r = 0; r < 4; r++) acc[mt][nt][r] = 0.f;

    auto issue = [&](int ks) {
        uint32_t bo = (uint32_t)(ks % 3) * BUFSTRIDE;
        int dt = ks * CHUNK;
        cpa16(saA + bo,      qh + gaoff + dt);
        cpa16(saA + bo + 32, qh + gaoff + dt + 16);
        cpa16(saB + bo,      kh + gboff + dt);
        cpa16(saB + bo + 32, kh + gboff + dt + 16);
        asm volatile("cp.async.commit_group;");
    };

    issue(0);
    issue(1);
#pragma unroll 1
    for (int ks = 0; ks < NSTAGE; ks++) {
        if (ks < NSTAGE - 1)
            asm volatile("cp.async.wait_group 1;");
        else
            asm volatile("cp.async.wait_group 0;");
        __syncthreads();
        if (ks + 2 < NSTAGE) issue(ks + 2);

        uint32_t bo = (uint32_t)(ks % 3) * BUFSTRIDE;
#pragma unroll
        for (int kh2 = 0; kh2 < 2; kh2++) {
            uint32_t ko = bo + kh2 * 32;
            uint32_t a[4][4], bf[2][4];
#pragma unroll
            for (int mt = 0; mt < 4; mt++)
                ldsm4(a[mt][0], a[mt][1], a[mt][2], a[mt][3], aAh + ko + mt * 1280);
#pragma unroll
            for (int nc = 0; nc < 2; nc++)
                ldsm4(bf[nc][0], bf[nc][1], bf[nc][2], bf[nc][3], aBh + ko + nc * 1280);
#pragma unroll
            for (int mt = 0; mt < 4; mt++)
#pragma unroll
                for (int nt = 0; nt < 4; nt++) {
                    int nc = nt >> 1, s = nt & 1;
                    mma16816(acc[mt][nt], a[mt], bf[nc][s], bf[nc][2 + s]);
                }
        }
    }

#pragma unroll
    for (int nt = 0; nt < 4; nt++) {
        int c = wn * 32 + nt * 8 + (lane & 3) * 2;
        bool ok0 = cmask[c] > 0, ok1 = cmask[c + 1] > 0;
#pragma unroll
        for (int mt = 0; mt < 4; mt++) {
            if (!ok0) { acc[mt][nt][0] = -3.0e38f; acc[mt][nt][2] = -3.0e38f; }
            if (!ok1) { acc[mt][nt][1] = -3.0e38f; acc[mt][nt][3] = -3.0e38f; }
        }
    }
    float rm[8];
#pragma unroll
    for (int i = 0; i < 8; i++) rm[i] = -3.0e38f;
#pragma unroll
    for (int nt = 0; nt < 4; nt++)
#pragma unroll
        for (int mt = 0; mt < 4; mt++) {
            rm[mt * 2]     = fmaxf(rm[mt * 2],     fmaxf(acc[mt][nt][0], acc[mt][nt][1]));
            rm[mt * 2 + 1] = fmaxf(rm[mt * 2 + 1], fmaxf(acc[mt][nt][2], acc[mt][nt][3]));
        }
#pragma unroll
    for (int i = 0; i < 8; i++) {
        rm[i] = fmaxf(rm[i], __shfl_xor_sync(0xffffffffu, rm[i], 1));
        rm[i] = fmaxf(rm[i], __shfl_xor_sync(0xffffffffu, rm[i], 2));
    }
    if ((lane & 3) == 0) {
        int g = lane >> 2;
#pragma unroll
        for (int mt = 0; mt < 4; mt++) {
            smax[wm * 64 + mt * 16 + g][wn]     = rm[mt * 2];
            smax[wm * 64 + mt * 16 + g + 8][wn] = rm[mt * 2 + 1];
        }
    }
    __syncthreads();
    if (tid < 128)
        rmax[tid] = fmaxf(fmaxf(smax[tid][0], smax[tid][1]),
                          fmaxf(smax[tid][2], smax[tid][3]));
    __syncthreads();

    {
        int g = lane >> 2;
#pragma unroll
        for (int mt = 0; mt < 4; mt++) {
            int r0 = wm * 64 + mt * 16 + g;
            float t0 = rmax[r0] - WWIN, t1 = rmax[r0 + 8] - WWIN;
#pragma unroll
            for (int nt = 0; nt < 4; nt++) {
                int c = wn * 32 + nt * 8 + (lane & 3) * 2;
                if (acc[mt][nt][0] >= t0) atomicOr(&bits[r0][c >> 5], 1u << (c & 31));
                if (acc[mt][nt][1] >= t0) atomicOr(&bits[r0][(c + 1) >> 5], 1u << ((c + 1) & 31));
                if (acc[mt][nt][2] >= t1) atomicOr(&bits[r0 + 8][c >> 5], 1u << (c & 31));
                if (acc[mt][nt][3] >= t1) atomicOr(&bits[r0 + 8][(c + 1) >> 5], 1u << ((c + 1) & 31));
            }
        }
    }
    __syncthreads();
    if (tid < 128) {
        size_t ro = ((size_t)b * QQ + m0 + tid) * NTILES + blockIdx.y;
        g_Mpart[ro] = rmax[tid];
        *(uint4*)&g_cand[ro * 4] = *(uint4*)&bits[tid][0];
    }
}

// ---------------- kernel 5: refine — exact max + M -----------------------------
__global__ void refine_kernel(const float* __restrict__ q,
                              const float* __restrict__ k, float Uf) {
    int row = blockIdx.x * 8 + (threadIdx.x >> 5);
    int lane = threadIdx.x & 31;
    if (row >= BB * QQ) return;
    int b = row / QQ;

    const float* mp = g_Mpart + (size_t)row * NTILES;
    float gmax = -3.0e38f;
#pragma unroll
    for (int t = 0; t < NTILES; t++) gmax = fmaxf(gmax, mp[t]);
    float thr = gmax - WWIN;

    const float* qr = q + (size_t)row * DD;
    const float* ws = g_wsum + b * DD;
    float qw = 0.f;
#pragma unroll
    for (int t = 0; t < DD / 32; t++)
        qw += qr[t * 32 + lane] * ws[t * 32 + lane];
#pragma unroll
    for (int off = 16; off > 0; off >>= 1)
        qw += __shfl_xor_sync(0xffffffffu, qw, off);

    const float* kb = k + (size_t)b * KVN * DD;
    float best = -3.0e38f;
#pragma unroll 1
    for (int t = 0; t < NTILES; t++) {
        if (mp[t] < thr) continue;
        const uint32_t* cw = g_cand + ((size_t)row * NTILES + t) * 4;
#pragma unroll
        for (int w = 0; w < 4; w++) {
            uint32_t m = cw[w];
            while (m) {
                int bit = __ffs(m) - 1;
                m &= m - 1;
                int col = t * 128 + w * 32 + bit;
                const float* kr = kb + (size_t)col * DD;
                float d = 0.f;
#pragma unroll
                for (int tt = 0; tt < DD / 32; tt++)
                    d += qr[tt * 32 + lane] * kr[tt * 32 + lane];
#pragma unroll
                for (int off = 16; off > 0; off >>= 1)
                    d += __shfl_xor_sync(0xffffffffu, d, off);
                best = fmaxf(best, d);
            }
        }
    }
    if (lane == 0) g_M[row] = best - qw / Uf;
}

// ---------------- kernel 6: top-60 tournament ------------------------------------
__global__ void topk_kernel() {
    int b = blockIdx.x;
    __shared__ unsigned long long keys[QQ];
    __shared__ unsigned long long warpmax[32];
    __shared__ int s_owner;
    int tid = threadIdx.x;
    int lane = tid & 31, warp = tid >> 5;

#pragma unroll
    for (int rep = 0; rep < 2; rep++) {
        int i = rep * 1024 + tid;
        uint32_t u = __float_as_uint(g_M[b * QQ + i]);
        u = (u & 0x80000000u) ? ~u : (u | 0x80000000u);
        keys[i] = ((unsigned long long)u << 32) | (unsigned long long)(QQ - 1 - i);
    }
    __syncthreads();

    {
        unsigned long long m0 = keys[warp * 64 + lane];
        unsigned long long m1 = keys[warp * 64 + 32 + lane];
        unsigned long long m = (m0 > m1) ? m0 : m1;
#pragma unroll
        for (int off = 16; off > 0; off >>= 1) {
            unsigned long long o = __shfl_xor_sync(0xffffffffu, m, off);
            m = (o > m) ? o : m;
        }
        if (lane == 0) warpmax[warp] = m;
    }
    __syncthreads();

    for (int it = 0; it < UQ; it++) {
        if (warp == 0) {
            unsigned long long m = warpmax[lane];
#pragma unroll
            for (int off = 16; off > 0; off >>= 1) {
                unsigned long long o = __shfl_xor_sync(0xffffffffu, m, off);
                m = (o > m) ? o : m;
            }
            if (lane == 0) {
                int i = QQ - 1 - (int)(m & 0xFFFFFFFFull);
                g_topidx[b * UQ + it] = i;
                keys[i] = 0ull;
                s_owner = i >> 6;
            }
        }
        __syncthreads();
        int ow = s_owner;
        if (warp == ow) {
            unsigned long long m0 = keys[ow * 64 + lane];
            unsigned long long m1 = keys[ow * 64 + 32 + lane];
            unsigned long long m = (m0 > m1) ? m0 : m1;
#pragma unroll
            for (int off = 16; off > 0; off >>= 1) {
                unsigned long long o = __shfl_xor_sync(0xffffffffu, m, off);
                m = (o > m) ? o : m;
            }
            if (lane == 0) warpmax[ow] = m;
        }
        __syncthreads();
    }
}

// ---------------- kernel 7: fill output with v-mean ------------------------------
__global__ void fill_kernel(float* __restrict__ out) {
    size_t f = (size_t)blockIdx.x * 256 + threadIdx.x;
    int d4 = (int)(f & (DD / 4 - 1));
    size_t row = f >> 7;
    int b = (int)(row >> 11);
    float4 val = *(const float4*)(g_vmean + b * DD + d4 * 4);
    ((float4*)out)[f] = val;
}

// ---------------- kernel 8: logits S1 = q_bar @ k^T * scale ----------------------
__global__ void __launch_bounds__(256)
logits_kernel(const float* __restrict__ q, const float* __restrict__ k) {
    int b = blockIdx.y;
    int n0 = blockIdx.x * 64;
    __shared__ int   tix[UQ];
    __shared__ float qs2[16][64];
    __shared__ float ks2[16][64];
    int tid = threadIdx.x;
    if (tid < UQ) tix[tid] = g_topidx[b * UQ + tid];

    int tx = tid & 15, ty = tid >> 4;
    float acc[4][4];
#pragma unroll
    for (int i = 0; i < 4; i++)
#pragma unroll
        for (int j = 0; j < 4; j++) acc[i][j] = 0.f;

    const float* qb = q + (size_t)b * QQ * DD;
    const float* kb = k + (size_t)b * KVN * DD;

    for (int dt = 0; dt < DD; dt += 16) {
        __syncthreads();
        if (tid < 240) {
            int i = tid >> 2, hh = (tid & 3) * 4;
            float4 v4 = *(const float4*)(qb + (size_t)tix[i] * DD + dt + hh);
            qs2[hh + 0][i] = v4.x; qs2[hh + 1][i] = v4.y;
            qs2[hh + 2][i] = v4.z; qs2[hh + 3][i] = v4.w;
        }
        {
            int r2 = tid >> 2, h2 = (tid & 3) * 4;
            float4 a4 = *(const float4*)(kb + (size_t)(n0 + r2) * DD + dt + h2);
            ks2[h2 + 0][r2] = a4.x; ks2[h2 + 1][r2] = a4.y;
            ks2[h2 + 2][r2] = a4.z; ks2[h2 + 3][r2] = a4.w;
        }
        __syncthreads();
#pragma unroll
        for (int kk = 0; kk < 16; kk++) {
            float a[4], bb[4];
            *(float4*)&a[0]  = *(float4*)&qs2[kk][ty * 4];
            *(float4*)&bb[0] = *(float4*)&ks2[kk][tx * 4];
#pragma unroll
            for (int i = 0; i < 4; i++)
#pragma unroll
                for (int j = 0; j < 4; j++)
                    acc[i][j] += a[i] * bb[j];
        }
    }
    float scale = rsqrtf((float)KVN);
#pragma unroll
    for (int ii = 0; ii < 4; ii++) {
        int i = ty * 4 + ii;
        if (i < UQ) {
#pragma unroll
            for (int j = 0; j < 4; j++)
                g_S1[((size_t)b * UQ + i) * KVN + n0 + tx * 4 + j] =
                    acc[ii][j] * scale;
        }
    }
}

// ---------------- kernel 9: row softmax ------------------------------------------
__global__ void softmax_kernel() {
    int row = blockIdx.x;
    float* p = g_S1 + (size_t)row * KVN;
    __shared__ float sred[256];
    int tid = threadIdx.x;

    float m = -3.4e38f;
    for (int i = tid; i < KVN; i += 256) m = fmaxf(m, p[i]);
    sred[tid] = m; __syncthreads();
    for (int s = 128; s > 0; s >>= 1) {
        if (tid < s) sred[tid] = fmaxf(sred[tid], sred[tid + s]);
        __syncthreads();
    }
    m = sred[0];
    __syncthreads();

    float sum = 0.f;
    for (int i = tid; i < KVN; i += 256) {
        float e = expf(p[i] - m);
        p[i] = e;
        sum += e;
    }
    sred[tid] = sum; __syncthreads();
    for (int s = 128; s > 0; s >>= 1) {
        if (tid < s) sred[tid] += sred[tid + s];
        __syncthreads();
    }
    float inv = 1.0f / sred[0];
    for (int i = tid; i < KVN; i += 256) p[i] *= inv;
}

// ---------------- kernel 10: O partials = P @ V (split kv) -----------------------
__global__ void __launch_bounds__(256)
pv_kernel(const float* __restrict__ v) {
    int b = blockIdx.z;
    int s = blockIdx.y;
    int d0 = blockIdx.x * 128;
    int kv0 = s * (KVN / PVS);     // 64

    __shared__ float ps[16][64];
    __shared__ float vs[16][128];
    int tid = threadIdx.x;
    int tx = tid & 15, ty = tid >> 4;
    float acc[4][8];
#pragma unroll
    for (int i = 0; i < 4; i++)
#pragma unroll
        for (int j = 0; j < 8; j++) acc[i][j] = 0.f;

    const float* vb = v + (size_t)b * KVN * DD;

    for (int kt = 0; kt < KVN / PVS; kt += 16) {
        __syncthreads();
        if (tid < 240) {
            int i = tid >> 2, hh = (tid & 3) * 4;
            float4 a4 = *(const float4*)(g_S1 + ((size_t)b * UQ + i) * KVN
                                         + kv0 + kt + hh);
            ps[hh + 0][i] = a4.x; ps[hh + 1][i] = a4.y;
            ps[hh + 2][i] = a4.z; ps[hh + 3][i] = a4.w;
        }
        {
            int kkr = tid >> 4, dc = (tid & 15) * 8;
            float4 a4 = *(const float4*)(vb + (size_t)(kv0 + kt + kkr) * DD + d0 + dc);
            float4 b4 = *(const float4*)(vb + (size_t)(kv0 + kt + kkr) * DD + d0 + dc + 4);
            vs[kkr][dc + 0] = a4.x; vs[kkr][dc + 1] = a4.y;
            vs[kkr][dc + 2] = a4.z; vs[kkr][dc + 3] = a4.w;
            vs[kkr][dc + 4] = b4.x; vs[kkr][dc + 5] = b4.y;
            vs[kkr][dc + 6] = b4.z; vs[kkr][dc + 7] = b4.w;
        }
        __syncthreads();
#pragma unroll
        for (int kk = 0; kk < 16; kk++) {
            float a[4], bb[8];
            *(float4*)&a[0]  = *(float4*)&ps[kk][ty * 4];
            *(float4*)&bb[0] = *(float4*)&vs[kk][tx * 8];
            *(float4*)&bb[4] = *(float4*)&vs[kk][tx * 8 + 4];
#pragma unroll
            for (int i = 0; i < 4; i++)
#pragma unroll
                for (int j = 0; j < 8; j++)
                    acc[i][j] += a[i] * bb[j];
        }
    }
#pragma unroll
    for (int ii = 0; ii < 4; ii++) {
        int i = ty * 4 + ii;
        if (i < UQ) {
#pragma unroll
            for (int j = 0; j < 8; j++)
                g_Opart[(((size_t)s * BB + b) * UQ + i) * DD + d0 + tx * 8 + j] =
                    acc[ii][j];
        }
    }
}

// ---------------- kernel 11: reduce PV partials + scatter ------------------------
__global__ void oreduce_kernel(float* __restrict__ out) {
    int idx = blockIdx.x * 256 + threadIdx.x;
    if (idx >= BB * UQ * DD) return;
    int d = idx % DD;
    int rest = idx / DD;
    int i = rest % UQ;
    int b = rest / UQ;
    float s = 0.f;
#pragma unroll
    for (int p = 0; p < PVS; p++)
        s += g_Opart[(((size_t)p * BB + b) * UQ + i) * DD + d];
    int row = g_topidx[b * UQ + i];
    out[((size_t)b * QQ + row) * DD + d] = s;
}

// ---------------- launch ----------------------------------------------------------
extern "C" void kernel_launch(void* const* d_in, const int* in_sizes, int n_in,
                              void* d_out, int out_size) {
    const float* q    = (const float*)d_in[0];
    const float* k    = (const float*)d_in[1];
    const float* v    = (const float*)d_in[2];
    const int*   sidx = (const int*)d_in[3];
    float* out = (float*)d_out;
    int U = in_sizes[3] / BB;

    split_kernel<<<(BB * QQ * DD / 4) / 256, 256>>>(q, k);
    zero_count_kernel<<<(BB * KVN + 255) / 256, 256>>>();
    count_kernel<<<(BB * U + 255) / 256, 256>>>(sidx, U);
    wsum_part_kernel<<<dim3(WS_SPLIT, BB), 512>>>(k, v);
    qkmax_tc_kernel<<<dim3(QQ / 128, KVN / 128, BB), 256>>>();
    wsum_reduce_kernel<<<8, 64>>>();
    refine_kernel<<<(BB * QQ) / 8, 256>>>(q, k, (float)U);
    topk_kernel<<<BB, 1024>>>();
    fill_kernel<<<(BB * QQ * DD / 4) / 256, 256>>>(out);
    logits_kernel<<<dim3(KVN / 64, BB), 256>>>(q, k);
    softmax_kernel<<<BB * UQ, 256>>>();
    pv_kernel<<<dim3(DD / 128, PVS, BB), 256>>>(v);
    oreduce_kernel<<<(BB * UQ * DD + 255) / 256, 256>>>(out);
}

// round 16
// speedup vs baseline: 1.0875x; 1.0216x over previous
#include <cuda_runtime.h>
#include <cuda_bf16.h>
#include <math.h>
#include <stdint.h>

// Problem constants
#define BB    4
#define QQ    2048
#define KVN   2048
#define DD    512
#define UQ    60
#define NTILES (KVN / 128)       // 16
#define WS_SPLIT 32
#define KVC   (KVN / WS_SPLIT)   // 64
#define PVS   16
#define CHUNK 32
#define NSTAGE (DD / CHUNK)      // 16
#define WWIN  1.0f               // rescue window (6-sigma bf16 dot err ~0.4)

// ---------------- scratch ----------------------------------------------------
__device__ int   g_count[BB * KVN];
__device__ float g_wspart[WS_SPLIT * BB * DD];
__device__ float g_vmpart[WS_SPLIT * BB * DD];
__device__ float g_wsum[BB * DD];
__device__ float g_vmean[BB * DD];
__device__ float g_M[BB * QQ];
__device__ float g_Mpart[BB * QQ * NTILES];
__device__ uint32_t g_cand[(size_t)BB * QQ * NTILES * 4];
__device__ int   g_topidx[BB * UQ];
__device__ float g_S1[(size_t)BB * UQ * KVN];
__device__ float g_Opart[(size_t)PVS * BB * UQ * DD];
__device__ __nv_bfloat16 g_qhi[(size_t)BB * QQ * DD];
__device__ __nv_bfloat16 g_khi[(size_t)BB * KVN * DD];

// ---------------- PTX helpers -------------------------------------------------
__device__ __forceinline__ uint32_t smem_u32(const void* p) {
    return (uint32_t)__cvta_generic_to_shared(p);
}
__device__ __forceinline__ void cpa16(uint32_t saddr, const void* g) {
    asm volatile("cp.async.cg.shared.global [%0], [%1], 16;" :: "r"(saddr), "l"(g));
}
__device__ __forceinline__ void ldsm4(uint32_t& r0, uint32_t& r1, uint32_t& r2,
                                      uint32_t& r3, uint32_t addr) {
    asm volatile("ldmatrix.sync.aligned.m8n8.x4.shared.b16 {%0,%1,%2,%3}, [%4];"
                 : "=r"(r0), "=r"(r1), "=r"(r2), "=r"(r3) : "r"(addr));
}
__device__ __forceinline__ void mma16816(float* c, const uint32_t* a,
                                         uint32_t b0, uint32_t b1) {
    asm volatile(
        "mma.sync.aligned.m16n8k16.row.col.f32.bf16.bf16.f32 "
        "{%0,%1,%2,%3}, {%4,%5,%6,%7}, {%8,%9}, {%0,%1,%2,%3};"
        : "+f"(c[0]), "+f"(c[1]), "+f"(c[2]), "+f"(c[3])
        : "r"(a[0]), "r"(a[1]), "r"(a[2]), "r"(a[3]), "r"(b0), "r"(b1));
}

// ---------------- kernel 0: bf16 hi of q and k ---------------------------------
__global__ void split_kernel(const float* __restrict__ q, const float* __restrict__ k) {
    size_t i = (size_t)blockIdx.x * 256 + threadIdx.x;   // float4 index
    float4 a = ((const float4*)q)[i];
    __nv_bfloat162 h01, h23;
    h01.x = __float2bfloat16(a.x); h01.y = __float2bfloat16(a.y);
    h23.x = __float2bfloat16(a.z); h23.y = __float2bfloat16(a.w);
    ((__nv_bfloat162*)g_qhi)[i * 2] = h01; ((__nv_bfloat162*)g_qhi)[i * 2 + 1] = h23;

    float4 bvec = ((const float4*)k)[i];
    h01.x = __float2bfloat16(bvec.x); h01.y = __float2bfloat16(bvec.y);
    h23.x = __float2bfloat16(bvec.z); h23.y = __float2bfloat16(bvec.w);
    ((__nv_bfloat162*)g_khi)[i * 2] = h01; ((__nv_bfloat162*)g_khi)[i * 2 + 1] = h23;
}

// ---------------- kernels 1,2: counts -----------------------------------------
__global__ void zero_count_kernel() {
    int i = blockIdx.x * blockDim.x + threadIdx.x;
    if (i < BB * KVN) g_count[i] = 0;
}
__global__ void count_kernel(const int* __restrict__ sidx, int U) {
    int i = blockIdx.x * blockDim.x + threadIdx.x;
    if (i < BB * U) {
        int b = i / U;
        atomicAdd(&g_count[b * KVN + sidx[i]], 1);
    }
}

// ---------------- kernel 3: weighted key sum + v mean --------------------------
// grid (WS_SPLIT=32, BB), block 512: 128 float4-cols x 4 row-groups of 16 rows.
__global__ void __launch_bounds__(512)
wsum_part_kernel(const float* __restrict__ k, const float* __restrict__ v) {
    int s = blockIdx.x;
    int b = blockIdx.y;
    int d4 = threadIdx.x & 127;    // float4 column 0..127
    int g  = threadIdx.x >> 7;     // row group 0..3

    __shared__ float  cntf[KVC];
    __shared__ float4 redw[4][128];
    __shared__ float4 redv[4][128];
    if (threadIdx.x < KVC)
        cntf[threadIdx.x] = (float)g_count[b * KVN + s * KVC + threadIdx.x];
    __syncthreads();

    const float4* kp = (const float4*)(k + ((size_t)b * KVN + (size_t)s * KVC) * DD) + d4;
    const float4* vp = (const float4*)(v + ((size_t)b * KVN + (size_t)s * KVC) * DD) + d4;
    float4 ws = make_float4(0.f, 0.f, 0.f, 0.f);
    float4 vm = make_float4(0.f, 0.f, 0.f, 0.f);
#pragma unroll
    for (int j = 0; j < 16; j++) {
        int row = g * 16 + j;
        float c = cntf[row];
        float4 kv = kp[(size_t)row * (DD / 4)];
        float4 vv = vp[(size_t)row * (DD / 4)];
        ws.x += c * kv.x; ws.y += c * kv.y; ws.z += c * kv.z; ws.w += c * kv.w;
        vm.x += vv.x;     vm.y += vv.y;     vm.z += vv.z;     vm.w += vv.w;
    }
    redw[g][d4] = ws;
    redv[g][d4] = vm;
    __syncthreads();
    if (g == 0) {
        float4 w0 = redw[0][d4], w1 = redw[1][d4], w2 = redw[2][d4], w3 = redw[3][d4];
        float4 v0 = redv[0][d4], v1 = redv[1][d4], v2 = redv[2][d4], v3 = redv[3][d4];
        float4 W, V;
        W.x = ((w0.x + w1.x) + w2.x) + w3.x;
        W.y = ((w0.y + w1.y) + w2.y) + w3.y;
        W.z = ((w0.z + w1.z) + w2.z) + w3.z;
        W.w = ((w0.w + w1.w) + w2.w) + w3.w;
        V.x = ((v0.x + v1.x) + v2.x) + v3.x;
        V.y = ((v0.y + v1.y) + v2.y) + v3.y;
        V.z = ((v0.z + v1.z) + v2.z) + v3.z;
        V.w = ((v0.w + v1.w) + v2.w) + v3.w;
        ((float4*)g_wspart)[((size_t)s * BB + b) * (DD / 4) + d4] = W;
        ((float4*)g_vmpart)[((size_t)s * BB + b) * (DD / 4) + d4] = V;
    }
}

// float4 over d: 8 blocks x 64 threads cover BB*DD/4 vectors (32 partials)
__global__ void wsum_reduce_kernel() {
    int idx = blockIdx.x * 64 + threadIdx.x;   // 0..511
    if (idx >= BB * DD / 4) return;
    float4 ws = make_float4(0.f, 0.f, 0.f, 0.f);
    float4 vm = make_float4(0.f, 0.f, 0.f, 0.f);
#pragma unroll
    for (int s = 0; s < WS_SPLIT; s++) {
        float4 a = ((const float4*)g_wspart)[(size_t)s * (BB * DD / 4) + idx];
        float4 c = ((const float4*)g_vmpart)[(size_t)s * (BB * DD / 4) + idx];
        ws.x += a.x; ws.y += a.y; ws.z += a.z; ws.w += a.w;
        vm.x += c.x; vm.y += c.y; vm.z += c.z; vm.w += c.w;
    }
    ((float4*)g_wsum)[idx] = ws;
    vm.x *= (1.0f / KVN); vm.y *= (1.0f / KVN);
    vm.z *= (1.0f / KVN); vm.w *= (1.0f / KVN);
    ((float4*)g_vmean)[idx] = vm;
}

// ---------------- kernel 4: approx QK^T (bf16 HMMA) -> rowmax + cand bits ------
__global__ void __launch_bounds__(256, 2)
qkmax_tc_kernel() {
    __shared__ __nv_bfloat16 sA[3][128][40];
    __shared__ __nv_bfloat16 sB[3][128][40];
    __shared__ int      cmask[128];
    __shared__ float    smax[128][4];
    __shared__ float    rmax[128];
    __shared__ uint32_t bits[128][4];

    const int tid = threadIdx.x, lane = tid & 31, warp = tid >> 5;
    const int wm = warp >> 2, wn = warp & 3;
    const int b = blockIdx.z;
    const int m0 = blockIdx.x * 128, n0 = blockIdx.y * 128;

    const __nv_bfloat16* qh = g_qhi + (size_t)b * QQ * DD;
    const __nv_bfloat16* kh = g_khi + (size_t)b * KVN * DD;

    if (tid < 128) {
        cmask[tid] = g_count[b * KVN + n0 + tid];
        bits[tid][0] = 0u; bits[tid][1] = 0u; bits[tid][2] = 0u; bits[tid][3] = 0u;
    }

    const int lrow = tid >> 1, lhalf = tid & 1;
    const size_t gaoff = (size_t)(m0 + lrow) * DD + lhalf * 8;
    const size_t gboff = (size_t)(n0 + lrow) * DD + lhalf * 8;
    const uint32_t saA = smem_u32(&sA[0][lrow][lhalf * 8]);
    const uint32_t saB = smem_u32(&sB[0][lrow][lhalf * 8]);
    const uint32_t BUFSTRIDE = 128 * 40 * 2;

    const int lr = lane & 15;
    const int lc8 = (lane >> 4) * 8;
    const uint32_t aAh = smem_u32(&sA[0][wm * 64 + lr][lc8]);
    const uint32_t aBh = smem_u32(&sB[0][wn * 32 + lr][lc8]);

    float acc[4][4][4];
#pragma unroll
    for (int mt = 0; mt < 4; mt++)
#pragma unroll
        for (int nt = 0; nt < 4; nt++)
#pragma unroll
            for (int r = 0; r < 4; r++) acc[mt][nt][r] = 0.f;

    auto issue = [&](int ks) {
        uint32_t bo = (uint32_t)(ks % 3) * BUFSTRIDE;
        int dt = ks * CHUNK;
        cpa16(saA + bo,      qh + gaoff + dt);
        cpa16(saA + bo + 32, qh + gaoff + dt + 16);
        cpa16(saB + bo,      kh + gboff + dt);
        cpa16(saB + bo + 32, kh + gboff + dt + 16);
        asm volatile("cp.async.commit_group;");
    };

    issue(0);
    issue(1);
#pragma unroll 1
    for (int ks = 0; ks < NSTAGE; ks++) {
        if (ks < NSTAGE - 1)
            asm volatile("cp.async.wait_group 1;");
        else
            asm volatile("cp.async.wait_group 0;");
        __syncthreads();
        if (ks + 2 < NSTAGE) issue(ks + 2);

        uint32_t bo = (uint32_t)(ks % 3) * BUFSTRIDE;
#pragma unroll
        for (int kh2 = 0; kh2 < 2; kh2++) {
            uint32_t ko = bo + kh2 * 32;
            uint32_t a[4][4], bf[2][4];
#pragma unroll
            for (int mt = 0; mt < 4; mt++)
                ldsm4(a[mt][0], a[mt][1], a[mt][2], a[mt][3], aAh + ko + mt * 1280);
#pragma unroll
            for (int nc = 0; nc < 2; nc++)
                ldsm4(bf[nc][0], bf[nc][1], bf[nc][2], bf[nc][3], aBh + ko + nc * 1280);
#pragma unroll
            for (int mt = 0; mt < 4; mt++)
#pragma unroll
                for (int nt = 0; nt < 4; nt++) {
                    int nc = nt >> 1, s = nt & 1;
                    mma16816(acc[mt][nt], a[mt], bf[nc][s], bf[nc][2 + s]);
                }
        }
    }

#pragma unroll
    for (int nt = 0; nt < 4; nt++) {
        int c = wn * 32 + nt * 8 + (lane & 3) * 2;
        bool ok0 = cmask[c] > 0, ok1 = cmask[c + 1] > 0;
#pragma unroll
        for (int mt = 0; mt < 4; mt++) {
            if (!ok0) { acc[mt][nt][0] = -3.0e38f; acc[mt][nt][2] = -3.0e38f; }
            if (!ok1) { acc[mt][nt][1] = -3.0e38f; acc[mt][nt][3] = -3.0e38f; }
        }
    }
    float rm[8];
#pragma unroll
    for (int i = 0; i < 8; i++) rm[i] = -3.0e38f;
#pragma unroll
    for (int nt = 0; nt < 4; nt++)
#pragma unroll
        for (int mt = 0; mt < 4; mt++) {
            rm[mt * 2]     = fmaxf(rm[mt * 2],     fmaxf(acc[mt][nt][0], acc[mt][nt][1]));
            rm[mt * 2 + 1] = fmaxf(rm[mt * 2 + 1], fmaxf(acc[mt][nt][2], acc[mt][nt][3]));
        }
#pragma unroll
    for (int i = 0; i < 8; i++) {
        rm[i] = fmaxf(rm[i], __shfl_xor_sync(0xffffffffu, rm[i], 1));
        rm[i] = fmaxf(rm[i], __shfl_xor_sync(0xffffffffu, rm[i], 2));
    }
    if ((lane & 3) == 0) {
        int g = lane >> 2;
#pragma unroll
        for (int mt = 0; mt < 4; mt++) {
            smax[wm * 64 + mt * 16 + g][wn]     = rm[mt * 2];
            smax[wm * 64 + mt * 16 + g + 8][wn] = rm[mt * 2 + 1];
        }
    }
    __syncthreads();
    if (tid < 128)
        rmax[tid] = fmaxf(fmaxf(smax[tid][0], smax[tid][1]),
                          fmaxf(smax[tid][2], smax[tid][3]));
    __syncthreads();

    {
        int g = lane >> 2;
#pragma unroll
        for (int mt = 0; mt < 4; mt++) {
            int r0 = wm * 64 + mt * 16 + g;
            float t0 = rmax[r0] - WWIN, t1 = rmax[r0 + 8] - WWIN;
#pragma unroll
            for (int nt = 0; nt < 4; nt++) {
                int c = wn * 32 + nt * 8 + (lane & 3) * 2;
                if (acc[mt][nt][0] >= t0) atomicOr(&bits[r0][c >> 5], 1u << (c & 31));
                if (acc[mt][nt][1] >= t0) atomicOr(&bits[r0][(c + 1) >> 5], 1u << ((c + 1) & 31));
                if (acc[mt][nt][2] >= t1) atomicOr(&bits[r0 + 8][c >> 5], 1u << (c & 31));
                if (acc[mt][nt][3] >= t1) atomicOr(&bits[r0 + 8][(c + 1) >> 5], 1u << ((c + 1) & 31));
            }
        }
    }
    __syncthreads();
    if (tid < 128) {
        size_t ro = ((size_t)b * QQ + m0 + tid) * NTILES + blockIdx.y;
        g_Mpart[ro] = rmax[tid];
        *(uint4*)&g_cand[ro * 4] = *(uint4*)&bits[tid][0];
    }
}

// ---------------- kernel 5: refine — exact max + M -----------------------------
__global__ void refine_kernel(const float* __restrict__ q,
                              const float* __restrict__ k, float Uf) {
    int row = blockIdx.x * 8 + (threadIdx.x >> 5);
    int lane = threadIdx.x & 31;
    if (row >= BB * QQ) return;
    int b = row / QQ;

    const float* mp = g_Mpart + (size_t)row * NTILES;
    float gmax = -3.0e38f;
#pragma unroll
    for (int t = 0; t < NTILES; t++) gmax = fmaxf(gmax, mp[t]);
    float thr = gmax - WWIN;

    const float* qr = q + (size_t)row * DD;
    const float* ws = g_wsum + b * DD;
    float qw = 0.f;
#pragma unroll
    for (int t = 0; t < DD / 32; t++)
        qw += qr[t * 32 + lane] * ws[t * 32 + lane];
#pragma unroll
    for (int off = 16; off > 0; off >>= 1)
        qw += __shfl_xor_sync(0xffffffffu, qw, off);

    const float* kb = k + (size_t)b * KVN * DD;
    float best = -3.0e38f;
#pragma unroll 1
    for (int t = 0; t < NTILES; t++) {
        if (mp[t] < thr) continue;
        const uint32_t* cw = g_cand + ((size_t)row * NTILES + t) * 4;
#pragma unroll
        for (int w = 0; w < 4; w++) {
            uint32_t m = cw[w];
            while (m) {
                int bit = __ffs(m) - 1;
                m &= m - 1;
                int col = t * 128 + w * 32 + bit;
                const float* kr = kb + (size_t)col * DD;
                float d = 0.f;
#pragma unroll
                for (int tt = 0; tt < DD / 32; tt++)
                    d += qr[tt * 32 + lane] * kr[tt * 32 + lane];
#pragma unroll
                for (int off = 16; off > 0; off >>= 1)
                    d += __shfl_xor_sync(0xffffffffu, d, off);
                best = fmaxf(best, d);
            }
        }
    }
    if (lane == 0) g_M[row] = best - qw / Uf;
}

// ---------------- kernel 6: top-60 tournament ------------------------------------
__global__ void topk_kernel() {
    int b = blockIdx.x;
    __shared__ unsigned long long keys[QQ];
    __shared__ unsigned long long warpmax[32];
    __shared__ int s_owner;
    int tid = threadIdx.x;
    int lane = tid & 31, warp = tid >> 5;

#pragma unroll
    for (int rep = 0; rep < 2; rep++) {
        int i = rep * 1024 + tid;
        uint32_t u = __float_as_uint(g_M[b * QQ + i]);
        u = (u & 0x80000000u) ? ~u : (u | 0x80000000u);
        keys[i] = ((unsigned long long)u << 32) | (unsigned long long)(QQ - 1 - i);
    }
    __syncthreads();

    {
        unsigned long long m0 = keys[warp * 64 + lane];
        unsigned long long m1 = keys[warp * 64 + 32 + lane];
        unsigned long long m = (m0 > m1) ? m0 : m1;
#pragma unroll
        for (int off = 16; off > 0; off >>= 1) {
            unsigned long long o = __shfl_xor_sync(0xffffffffu, m, off);
            m = (o > m) ? o : m;
        }
        if (lane == 0) warpmax[warp] = m;
    }
    __syncthreads();

    for (int it = 0; it < UQ; it++) {
        if (warp == 0) {
            unsigned long long m = warpmax[lane];
#pragma unroll
            for (int off = 16; off > 0; off >>= 1) {
                unsigned long long o = __shfl_xor_sync(0xffffffffu, m, off);
                m = (o > m) ? o : m;
            }
            if (lane == 0) {
                int i = QQ - 1 - (int)(m & 0xFFFFFFFFull);
                g_topidx[b * UQ + it] = i;
                keys[i] = 0ull;
                s_owner = i >> 6;
            }
        }
        __syncthreads();
        int ow = s_owner;
        if (warp == ow) {
            unsigned long long m0 = keys[ow * 64 + lane];
            unsigned long long m1 = keys[ow * 64 + 32 + lane];
            unsigned long long m = (m0 > m1) ? m0 : m1;
#pragma unroll
            for (int off = 16; off > 0; off >>= 1) {
                unsigned long long o = __shfl_xor_sync(0xffffffffu, m, off);
                m = (o > m) ? o : m;
            }
            if (lane == 0) warpmax[ow] = m;
        }
        __syncthreads();
    }
}

// ---------------- kernel 7: fill output with v-mean ------------------------------
__global__ void fill_kernel(float* __restrict__ out) {
    size_t f = (size_t)blockIdx.x * 256 + threadIdx.x;
    int d4 = (int)(f & (DD / 4 - 1));
    size_t row = f >> 7;
    int b = (int)(row >> 11);
    float4 val = *(const float4*)(g_vmean + b * DD + d4 * 4);
    ((float4*)out)[f] = val;
}

// ---------------- kernel 8: logits S1 = q_bar @ k^T * scale ----------------------
__global__ void __launch_bounds__(256)
logits_kernel(const float* __restrict__ q, const float* __restrict__ k) {
    int b = blockIdx.y;
    int n0 = blockIdx.x * 64;
    __shared__ int   tix[UQ];
    __shared__ float qs2[16][64];
    __shared__ float ks2[16][64];
    int tid = threadIdx.x;
    if (tid < UQ) tix[tid] = g_topidx[b * UQ + tid];

    int tx = tid & 15, ty = tid >> 4;
    float acc[4][4];
#pragma unroll
    for (int i = 0; i < 4; i++)
#pragma unroll
        for (int j = 0; j < 4; j++) acc[i][j] = 0.f;

    const float* qb = q + (size_t)b * QQ * DD;
    const float* kb = k + (size_t)b * KVN * DD;

    for (int dt = 0; dt < DD; dt += 16) {
        __syncthreads();
        if (tid < 240) {
            int i = tid >> 2, hh = (tid & 3) * 4;
            float4 v4 = *(const float4*)(qb + (size_t)tix[i] * DD + dt + hh);
            qs2[hh + 0][i] = v4.x; qs2[hh + 1][i] = v4.y;
            qs2[hh + 2][i] = v4.z; qs2[hh + 3][i] = v4.w;
        }
        {
            int r2 = tid >> 2, h2 = (tid & 3) * 4;
            float4 a4 = *(const float4*)(kb + (size_t)(n0 + r2) * DD + dt + h2);
            ks2[h2 + 0][r2] = a4.x; ks2[h2 + 1][r2] = a4.y;
            ks2[h2 + 2][r2] = a4.z; ks2[h2 + 3][r2] = a4.w;
        }
        __syncthreads();
#pragma unroll
        for (int kk = 0; kk < 16; kk++) {
            float a[4], bb[4];
            *(float4*)&a[0]  = *(float4*)&qs2[kk][ty * 4];
            *(float4*)&bb[0] = *(float4*)&ks2[kk][tx * 4];
#pragma unroll
            for (int i = 0; i < 4; i++)
#pragma unroll
                for (int j = 0; j < 4; j++)
                    acc[i][j] += a[i] * bb[j];
        }
    }
    float scale = rsqrtf((float)KVN);
#pragma unroll
    for (int ii = 0; ii < 4; ii++) {
        int i = ty * 4 + ii;
        if (i < UQ) {
#pragma unroll
            for (int j = 0; j < 4; j++)
                g_S1[((size_t)b * UQ + i) * KVN + n0 + tx * 4 + j] =
                    acc[ii][j] * scale;
        }
    }
}

// ---------------- kernel 9: row softmax ------------------------------------------
__global__ void softmax_kernel() {
    int row = blockIdx.x;
    float* p = g_S1 + (size_t)row * KVN;
    __shared__ float sred[256];
    int tid = threadIdx.x;

    float m = -3.4e38f;
    for (int i = tid; i < KVN; i += 256) m = fmaxf(m, p[i]);
    sred[tid] = m; __syncthreads();
    for (int s = 128; s > 0; s >>= 1) {
        if (tid < s) sred[tid] = fmaxf(sred[tid], sred[tid + s]);
        __syncthreads();
    }
    m = sred[0];
    __syncthreads();

    float sum = 0.f;
    for (int i = tid; i < KVN; i += 256) {
        float e = expf(p[i] - m);
        p[i] = e;
        sum += e;
    }
    sred[tid] = sum; __syncthreads();
    for (int s = 128; s > 0; s >>= 1) {
        if (tid < s) sred[tid] += sred[tid + s];
        __syncthreads();
    }
    float inv = 1.0f / sred[0];
    for (int i = tid; i < KVN; i += 256) p[i] *= inv;
}

// ---------------- kernel 10: O partials = P @ V (split kv, PVS=16) ---------------
__global__ void __launch_bounds__(256)
pv_kernel(const float* __restrict__ v) {
    int b = blockIdx.z;
    int s = blockIdx.y;
    int d0 = blockIdx.x * 128;
    int kv0 = s * (KVN / PVS);     // 128

    __shared__ float ps[16][64];
    __shared__ float vs[16][128];
    int tid = threadIdx.x;
    int tx = tid & 15, ty = tid >> 4;
    float acc[4][8];
#pragma unroll
    for (int i = 0; i < 4; i++)
#pragma unroll
        for (int j = 0; j < 8; j++) acc[i][j] = 0.f;

    const float* vb = v + (size_t)b * KVN * DD;

    for (int kt = 0; kt < KVN / PVS; kt += 16) {
        __syncthreads();
        if (tid < 240) {
            int i = tid >> 2, hh = (tid & 3) * 4;
            float4 a4 = *(const float4*)(g_S1 + ((size_t)b * UQ + i) * KVN
                                         + kv0 + kt + hh);
            ps[hh + 0][i] = a4.x; ps[hh + 1][i] = a4.y;
            ps[hh + 2][i] = a4.z; ps[hh + 3][i] = a4.w;
        }
        {
            int kkr = tid >> 4, dc = (tid & 15) * 8;
            float4 a4 = *(const float4*)(vb + (size_t)(kv0 + kt + kkr) * DD + d0 + dc);
            float4 b4 = *(const float4*)(vb + (size_t)(kv0 + kt + kkr) * DD + d0 + dc + 4);
            vs[kkr][dc + 0] = a4.x; vs[kkr][dc + 1] = a4.y;
            vs[kkr][dc + 2] = a4.z; vs[kkr][dc + 3] = a4.w;
            vs[kkr][dc + 4] = b4.x; vs[kkr][dc + 5] = b4.y;
            vs[kkr][dc + 6] = b4.z; vs[kkr][dc + 7] = b4.w;
        }
        __syncthreads();
#pragma unroll
        for (int kk = 0; kk < 16; kk++) {
            float a[4], bb[8];
            *(float4*)&a[0]  = *(float4*)&ps[kk][ty * 4];
            *(float4*)&bb[0] = *(float4*)&vs[kk][tx * 8];
            *(float4*)&bb[4] = *(float4*)&vs[kk][tx * 8 + 4];
#pragma unroll
            for (int i = 0; i < 4; i++)
#pragma unroll
                for (int j = 0; j < 8; j++)
                    acc[i][j] += a[i] * bb[j];
        }
    }
#pragma unroll
    for (int ii = 0; ii < 4; ii++) {
        int i = ty * 4 + ii;
        if (i < UQ) {
#pragma unroll
            for (int j = 0; j < 8; j++)
                g_Opart[(((size_t)s * BB + b) * UQ + i) * DD + d0 + tx * 8 + j] =
                    acc[ii][j];
        }
    }
}

// ---------------- kernel 11: reduce PV partials + scatter ------------------------
__global__ void oreduce_kernel(float* __restrict__ out) {
    int idx = blockIdx.x * 256 + threadIdx.x;
    if (idx >= BB * UQ * DD) return;
    int d = idx % DD;
    int rest = idx / DD;
    int i = rest % UQ;
    int b = rest / UQ;
    float s = 0.f;
#pragma unroll
    for (int p = 0; p < PVS; p++)
        s += g_Opart[(((size_t)p * BB + b) * UQ + i) * DD + d];
    int row = g_topidx[b * UQ + i];
    out[((size_t)b * QQ + row) * DD + d] = s;
}

// ---------------- launch ----------------------------------------------------------
extern "C" void kernel_launch(void* const* d_in, const int* in_sizes, int n_in,
                              void* d_out, int out_size) {
    const float* q    = (const float*)d_in[0];
    const float* k    = (const float*)d_in[1];
    const float* v    = (const float*)d_in[2];
    const int*   sidx = (const int*)d_in[3];
    float* out = (float*)d_out;
    int U = in_sizes[3] / BB;

    split_kernel<<<(BB * QQ * DD / 4) / 256, 256>>>(q, k);
    zero_count_kernel<<<(BB * KVN + 255) / 256, 256>>>();
    count_kernel<<<(BB * U + 255) / 256, 256>>>(sidx, U);
    wsum_part_kernel<<<dim3(WS_SPLIT, BB), 512>>>(k, v);
    qkmax_tc_kernel<<<dim3(QQ / 128, KVN / 128, BB), 256>>>();
    wsum_reduce_kernel<<<8, 64>>>();
    refine_kernel<<<(BB * QQ) / 8, 256>>>(q, k, (float)U);
    topk_kernel<<<BB, 1024>>>();
    fill_kernel<<<(BB * QQ * DD / 4) / 256, 256>>>(out);
    logits_kernel<<<dim3(KVN / 64, BB), 256>>>(q, k);
    softmax_kernel<<<BB * UQ, 256>>>();
    pv_kernel<<<dim3(DD / 128, PVS, BB), 256>>>(v);
    oreduce_kernel<<<(BB * UQ * DD + 255) / 256, 256>>>(out);
}

// round 17
// speedup vs baseline: 1.0954x; 1.0073x over previous
#include <cuda_runtime.h>
#include <cuda_bf16.h>
#include <math.h>
#include <stdint.h>

// Problem constants
#define BB    4
#define QQ    2048
#define KVN   2048
#define DD    512
#define UQ    60
#define NTILES (KVN / 128)       // 16
#define WS_SPLIT 32
#define KVC   (KVN / WS_SPLIT)   // 64
#define PVS   16
#define CHUNK 32
#define NSTAGE (DD / CHUNK)      // 16
#define WWIN  1.0f               // rescue window (6-sigma bf16 dot err ~0.4)

// ---------------- scratch ----------------------------------------------------
__device__ int   g_count[BB * KVN];
__device__ float g_wspart[WS_SPLIT * BB * DD];
__device__ float g_vmpart[WS_SPLIT * BB * DD];
__device__ float g_wsum[BB * DD];
__device__ float g_vmean[BB * DD];
__device__ float g_M[BB * QQ];
__device__ float g_Mpart[BB * QQ * NTILES];
__device__ uint32_t g_cand[(size_t)BB * QQ * NTILES * 4];
__device__ int   g_topidx[BB * UQ];
__device__ float g_S1[(size_t)BB * UQ * KVN];
__device__ float g_Opart[(size_t)PVS * BB * UQ * DD];
__device__ __nv_bfloat16 g_qhi[(size_t)BB * QQ * DD];
__device__ __nv_bfloat16 g_khi[(size_t)BB * KVN * DD];

// ---------------- PTX helpers -------------------------------------------------
__device__ __forceinline__ uint32_t smem_u32(const void* p) {
    return (uint32_t)__cvta_generic_to_shared(p);
}
__device__ __forceinline__ void cpa16(uint32_t saddr, const void* g) {
    asm volatile("cp.async.cg.shared.global [%0], [%1], 16;" :: "r"(saddr), "l"(g));
}
__device__ __forceinline__ void ldsm4(uint32_t& r0, uint32_t& r1, uint32_t& r2,
                                      uint32_t& r3, uint32_t addr) {
    asm volatile("ldmatrix.sync.aligned.m8n8.x4.shared.b16 {%0,%1,%2,%3}, [%4];"
                 : "=r"(r0), "=r"(r1), "=r"(r2), "=r"(r3) : "r"(addr));
}
__device__ __forceinline__ void mma16816(float* c, const uint32_t* a,
                                         uint32_t b0, uint32_t b1) {
    asm volatile(
        "mma.sync.aligned.m16n8k16.row.col.f32.bf16.bf16.f32 "
        "{%0,%1,%2,%3}, {%4,%5,%6,%7}, {%8,%9}, {%0,%1,%2,%3};"
        : "+f"(c[0]), "+f"(c[1]), "+f"(c[2]), "+f"(c[3])
        : "r"(a[0]), "r"(a[1]), "r"(a[2]), "r"(a[3]), "r"(b0), "r"(b1));
}

// ---------------- kernel 0: bf16 hi of q,k + zero counts ------------------------
__global__ void split_zero_kernel(const float* __restrict__ q,
                                  const float* __restrict__ k) {
    size_t i = (size_t)blockIdx.x * 256 + threadIdx.x;   // float4 index
    if (i < BB * KVN) g_count[i] = 0;

    float4 a = ((const float4*)q)[i];
    __nv_bfloat162 h01, h23;
    h01.x = __float2bfloat16(a.x); h01.y = __float2bfloat16(a.y);
    h23.x = __float2bfloat16(a.z); h23.y = __float2bfloat16(a.w);
    ((__nv_bfloat162*)g_qhi)[i * 2] = h01; ((__nv_bfloat162*)g_qhi)[i * 2 + 1] = h23;

    float4 bvec = ((const float4*)k)[i];
    h01.x = __float2bfloat16(bvec.x); h01.y = __float2bfloat16(bvec.y);
    h23.x = __float2bfloat16(bvec.z); h23.y = __float2bfloat16(bvec.w);
    ((__nv_bfloat162*)g_khi)[i * 2] = h01; ((__nv_bfloat162*)g_khi)[i * 2 + 1] = h23;
}

// ---------------- kernel 2: histogram -------------------------------------------
__global__ void count_kernel(const int* __restrict__ sidx, int U) {
    int i = blockIdx.x * blockDim.x + threadIdx.x;
    if (i < BB * U) {
        int b = i / U;
        atomicAdd(&g_count[b * KVN + sidx[i]], 1);
    }
}

// ---------------- kernel 3: weighted key sum + v mean --------------------------
// grid (WS_SPLIT=32, BB), block 512: 128 float4-cols x 4 row-groups of 16 rows.
__global__ void __launch_bounds__(512)
wsum_part_kernel(const float* __restrict__ k, const float* __restrict__ v) {
    int s = blockIdx.x;
    int b = blockIdx.y;
    int d4 = threadIdx.x & 127;    // float4 column 0..127
    int g  = threadIdx.x >> 7;     // row group 0..3

    __shared__ float  cntf[KVC];
    __shared__ float4 redw[4][128];
    __shared__ float4 redv[4][128];
    if (threadIdx.x < KVC)
        cntf[threadIdx.x] = (float)g_count[b * KVN + s * KVC + threadIdx.x];
    __syncthreads();

    const float4* kp = (const float4*)(k + ((size_t)b * KVN + (size_t)s * KVC) * DD) + d4;
    const float4* vp = (const float4*)(v + ((size_t)b * KVN + (size_t)s * KVC) * DD) + d4;
    float4 ws = make_float4(0.f, 0.f, 0.f, 0.f);
    float4 vm = make_float4(0.f, 0.f, 0.f, 0.f);
#pragma unroll
    for (int j = 0; j < 16; j++) {
        int row = g * 16 + j;
        float c = cntf[row];
        float4 kv = kp[(size_t)row * (DD / 4)];
        float4 vv = vp[(size_t)row * (DD / 4)];
        ws.x += c * kv.x; ws.y += c * kv.y; ws.z += c * kv.z; ws.w += c * kv.w;
        vm.x += vv.x;     vm.y += vv.y;     vm.z += vv.z;     vm.w += vv.w;
    }
    redw[g][d4] = ws;
    redv[g][d4] = vm;
    __syncthreads();
    if (g == 0) {
        float4 w0 = redw[0][d4], w1 = redw[1][d4], w2 = redw[2][d4], w3 = redw[3][d4];
        float4 v0 = redv[0][d4], v1 = redv[1][d4], v2 = redv[2][d4], v3 = redv[3][d4];
        float4 W, V;
        W.x = ((w0.x + w1.x) + w2.x) + w3.x;
        W.y = ((w0.y + w1.y) + w2.y) + w3.y;
        W.z = ((w0.z + w1.z) + w2.z) + w3.z;
        W.w = ((w0.w + w1.w) + w2.w) + w3.w;
        V.x = ((v0.x + v1.x) + v2.x) + v3.x;
        V.y = ((v0.y + v1.y) + v2.y) + v3.y;
        V.z = ((v0.z + v1.z) + v2.z) + v3.z;
        V.w = ((v0.w + v1.w) + v2.w) + v3.w;
        ((float4*)g_wspart)[((size_t)s * BB + b) * (DD / 4) + d4] = W;
        ((float4*)g_vmpart)[((size_t)s * BB + b) * (DD / 4) + d4] = V;
    }
}

// float4 over d: 8 blocks x 64 threads cover BB*DD/4 vectors (32 partials)
__global__ void wsum_reduce_kernel() {
    int idx = blockIdx.x * 64 + threadIdx.x;   // 0..511
    if (idx >= BB * DD / 4) return;
    float4 ws = make_float4(0.f, 0.f, 0.f, 0.f);
    float4 vm = make_float4(0.f, 0.f, 0.f, 0.f);
#pragma unroll
    for (int s = 0; s < WS_SPLIT; s++) {
        float4 a = ((const float4*)g_wspart)[(size_t)s * (BB * DD / 4) + idx];
        float4 c = ((const float4*)g_vmpart)[(size_t)s * (BB * DD / 4) + idx];
        ws.x += a.x; ws.y += a.y; ws.z += a.z; ws.w += a.w;
        vm.x += c.x; vm.y += c.y; vm.z += c.z; vm.w += c.w;
    }
    ((float4*)g_wsum)[idx] = ws;
    vm.x *= (1.0f / KVN); vm.y *= (1.0f / KVN);
    vm.z *= (1.0f / KVN); vm.w *= (1.0f / KVN);
    ((float4*)g_vmean)[idx] = vm;
}

// ---------------- kernel 4: approx QK^T (bf16 HMMA) -> rowmax + cand bits ------
__global__ void __launch_bounds__(256, 2)
qkmax_tc_kernel() {
    __shared__ __nv_bfloat16 sA[3][128][40];
    __shared__ __nv_bfloat16 sB[3][128][40];
    __shared__ int      cmask[128];
    __shared__ float    smax[128][4];
    __shared__ float    rmax[128];
    __shared__ uint32_t bits[128][4];

    const int tid = threadIdx.x, lane = tid & 31, warp = tid >> 5;
    const int wm = warp >> 2, wn = warp & 3;
    const int b = blockIdx.z;
    const int m0 = blockIdx.x * 128, n0 = blockIdx.y * 128;

    const __nv_bfloat16* qh = g_qhi + (size_t)b * QQ * DD;
    const __nv_bfloat16* kh = g_khi + (size_t)b * KVN * DD;

    if (tid < 128) {
        cmask[tid] = g_count[b * KVN + n0 + tid];
        bits[tid][0] = 0u; bits[tid][1] = 0u; bits[tid][2] = 0u; bits[tid][3] = 0u;
    }

    const int lrow = tid >> 1, lhalf = tid & 1;
    const size_t gaoff = (size_t)(m0 + lrow) * DD + lhalf * 8;
    const size_t gboff = (size_t)(n0 + lrow) * DD + lhalf * 8;
    const uint32_t saA = smem_u32(&sA[0][lrow][lhalf * 8]);
    const uint32_t saB = smem_u32(&sB[0][lrow][lhalf * 8]);
    const uint32_t BUFSTRIDE = 128 * 40 * 2;

    const int lr = lane & 15;
    const int lc8 = (lane >> 4) * 8;
    const uint32_t aAh = smem_u32(&sA[0][wm * 64 + lr][lc8]);
    const uint32_t aBh = smem_u32(&sB[0][wn * 32 + lr][lc8]);

    float acc[4][4][4];
#pragma unroll
    for (int mt = 0; mt < 4; mt++)
#pragma unroll
        for (int nt = 0; nt < 4; nt++)
#pragma unroll
            for (int r = 0; r < 4; r++) acc[mt][nt][r] = 0.f;

    auto issue = [&](int ks) {
        uint32_t bo = (uint32_t)(ks % 3) * BUFSTRIDE;
        int dt = ks * CHUNK;
        cpa16(saA + bo,      qh + gaoff + dt);
        cpa16(saA + bo + 32, qh + gaoff + dt + 16);
        cpa16(saB + bo,      kh + gboff + dt);
        cpa16(saB + bo + 32, kh + gboff + dt + 16);
        asm volatile("cp.async.commit_group;");
    };

    issue(0);
    issue(1);
#pragma unroll 1
    for (int ks = 0; ks < NSTAGE; ks++) {
        if (ks < NSTAGE - 1)
            asm volatile("cp.async.wait_group 1;");
        else
            asm volatile("cp.async.wait_group 0;");
        __syncthreads();
        if (ks + 2 < NSTAGE) issue(ks + 2);

        uint32_t bo = (uint32_t)(ks % 3) * BUFSTRIDE;
#pragma unroll
        for (int kh2 = 0; kh2 < 2; kh2++) {
            uint32_t ko = bo + kh2 * 32;
            uint32_t a[4][4], bf[2][4];
#pragma unroll
            for (int mt = 0; mt < 4; mt++)
                ldsm4(a[mt][0], a[mt][1], a[mt][2], a[mt][3], aAh + ko + mt * 1280);
#pragma unroll
            for (int nc = 0; nc < 2; nc++)
                ldsm4(bf[nc][0], bf[nc][1], bf[nc][2], bf[nc][3], aBh + ko + nc * 1280);
#pragma unroll
            for (int mt = 0; mt < 4; mt++)
#pragma unroll
                for (int nt = 0; nt < 4; nt++) {
                    int nc = nt >> 1, s = nt & 1;
                    mma16816(acc[mt][nt], a[mt], bf[nc][s], bf[nc][2 + s]);
                }
        }
    }

#pragma unroll
    for (int nt = 0; nt < 4; nt++) {
        int c = wn * 32 + nt * 8 + (lane & 3) * 2;
        bool ok0 = cmask[c] > 0, ok1 = cmask[c + 1] > 0;
#pragma unroll
        for (int mt = 0; mt < 4; mt++) {
            if (!ok0) { acc[mt][nt][0] = -3.0e38f; acc[mt][nt][2] = -3.0e38f; }
            if (!ok1) { acc[mt][nt][1] = -3.0e38f; acc[mt][nt][3] = -3.0e38f; }
        }
    }
    float rm[8];
#pragma unroll
    for (int i = 0; i < 8; i++) rm[i] = -3.0e38f;
#pragma unroll
    for (int nt = 0; nt < 4; nt++)
#pragma unroll
        for (int mt = 0; mt < 4; mt++) {
            rm[mt * 2]     = fmaxf(rm[mt * 2],     fmaxf(acc[mt][nt][0], acc[mt][nt][1]));
            rm[mt * 2 + 1] = fmaxf(rm[mt * 2 + 1], fmaxf(acc[mt][nt][2], acc[mt][nt][3]));
        }
#pragma unroll
    for (int i = 0; i < 8; i++) {
        rm[i] = fmaxf(rm[i], __shfl_xor_sync(0xffffffffu, rm[i], 1));
        rm[i] = fmaxf(rm[i], __shfl_xor_sync(0xffffffffu, rm[i], 2));
    }
    if ((lane & 3) == 0) {
        int g = lane >> 2;
#pragma unroll
        for (int mt = 0; mt < 4; mt++) {
            smax[wm * 64 + mt * 16 + g][wn]     = rm[mt * 2];
            smax[wm * 64 + mt * 16 + g + 8][wn] = rm[mt * 2 + 1];
        }
    }
    __syncthreads();
    if (tid < 128)
        rmax[tid] = fmaxf(fmaxf(smax[tid][0], smax[tid][1]),
                          fmaxf(smax[tid][2], smax[tid][3]));
    __syncthreads();

    {
        int g = lane >> 2;
#pragma unroll
        for (int mt = 0; mt < 4; mt++) {
            int r0 = wm * 64 + mt * 16 + g;
            float t0 = rmax[r0] - WWIN, t1 = rmax[r0 + 8] - WWIN;
#pragma unroll
            for (int nt = 0; nt < 4; nt++) {
                int c = wn * 32 + nt * 8 + (lane & 3) * 2;
                if (acc[mt][nt][0] >= t0) atomicOr(&bits[r0][c >> 5], 1u << (c & 31));
                if (acc[mt][nt][1] >= t0) atomicOr(&bits[r0][(c + 1) >> 5], 1u << ((c + 1) & 31));
                if (acc[mt][nt][2] >= t1) atomicOr(&bits[r0 + 8][c >> 5], 1u << (c & 31));
                if (acc[mt][nt][3] >= t1) atomicOr(&bits[r0 + 8][(c + 1) >> 5], 1u << ((c + 1) & 31));
            }
        }
    }
    __syncthreads();
    if (tid < 128) {
        size_t ro = ((size_t)b * QQ + m0 + tid) * NTILES + blockIdx.y;
        g_Mpart[ro] = rmax[tid];
        *(uint4*)&g_cand[ro * 4] = *(uint4*)&bits[tid][0];
    }
}

// ---------------- kernel 5: refine — exact max + M -----------------------------
__global__ void refine_kernel(const float* __restrict__ q,
                              const float* __restrict__ k, float Uf) {
    int row = blockIdx.x * 8 + (threadIdx.x >> 5);
    int lane = threadIdx.x & 31;
    if (row >= BB * QQ) return;
    int b = row / QQ;

    const float* mp = g_Mpart + (size_t)row * NTILES;
    float gmax = -3.0e38f;
#pragma unroll
    for (int t = 0; t < NTILES; t++) gmax = fmaxf(gmax, mp[t]);
    float thr = gmax - WWIN;

    const float* qr = q + (size_t)row * DD;
    const float* ws = g_wsum + b * DD;
    float qw = 0.f;
#pragma unroll
    for (int t = 0; t < DD / 32; t++)
        qw += qr[t * 32 + lane] * ws[t * 32 + lane];
#pragma unroll
    for (int off = 16; off > 0; off >>= 1)
        qw += __shfl_xor_sync(0xffffffffu, qw, off);

    const float* kb = k + (size_t)b * KVN * DD;
    float best = -3.0e38f;
#pragma unroll 1
    for (int t = 0; t < NTILES; t++) {
        if (mp[t] < thr) continue;
        const uint32_t* cw = g_cand + ((size_t)row * NTILES + t) * 4;
#pragma unroll
        for (int w = 0; w < 4; w++) {
            uint32_t m = cw[w];
            while (m) {
                int bit = __ffs(m) - 1;
                m &= m - 1;
                int col = t * 128 + w * 32 + bit;
                const float* kr = kb + (size_t)col * DD;
                float d = 0.f;
#pragma unroll
                for (int tt = 0; tt < DD / 32; tt++)
                    d += qr[tt * 32 + lane] * kr[tt * 32 + lane];
#pragma unroll
                for (int off = 16; off > 0; off >>= 1)
                    d += __shfl_xor_sync(0xffffffffu, d, off);
                best = fmaxf(best, d);
            }
        }
    }
    if (lane == 0) g_M[row] = best - qw / Uf;
}

// ---------------- kernel 6: top-60 tournament ------------------------------------
__global__ void topk_kernel() {
    int b = blockIdx.x;
    __shared__ unsigned long long keys[QQ];
    __shared__ unsigned long long warpmax[32];
    __shared__ int s_owner;
    int tid = threadIdx.x;
    int lane = tid & 31, warp = tid >> 5;

#pragma unroll
    for (int rep = 0; rep < 2; rep++) {
        int i = rep * 1024 + tid;
        uint32_t u = __float_as_uint(g_M[b * QQ + i]);
        u = (u & 0x80000000u) ? ~u : (u | 0x80000000u);
        keys[i] = ((unsigned long long)u << 32) | (unsigned long long)(QQ - 1 - i);
    }
    __syncthreads();

    {
        unsigned long long m0 = keys[warp * 64 + lane];
        unsigned long long m1 = keys[warp * 64 + 32 + lane];
        unsigned long long m = (m0 > m1) ? m0 : m1;
#pragma unroll
        for (int off = 16; off > 0; off >>= 1) {
            unsigned long long o = __shfl_xor_sync(0xffffffffu, m, off);
            m = (o > m) ? o : m;
        }
        if (lane == 0) warpmax[warp] = m;
    }
    __syncthreads();

    for (int it = 0; it < UQ; it++) {
        if (warp == 0) {
            unsigned long long m = warpmax[lane];
#pragma unroll
            for (int off = 16; off > 0; off >>= 1) {
                unsigned long long o = __shfl_xor_sync(0xffffffffu, m, off);
                m = (o > m) ? o : m;
            }
            if (lane == 0) {
                int i = QQ - 1 - (int)(m & 0xFFFFFFFFull);
                g_topidx[b * UQ + it] = i;
                keys[i] = 0ull;
                s_owner = i >> 6;
            }
        }
        __syncthreads();
        int ow = s_owner;
        if (warp == ow) {
            unsigned long long m0 = keys[ow * 64 + lane];
            unsigned long long m1 = keys[ow * 64 + 32 + lane];
            unsigned long long m = (m0 > m1) ? m0 : m1;
#pragma unroll
            for (int off = 16; off > 0; off >>= 1) {
                unsigned long long o = __shfl_xor_sync(0xffffffffu, m, off);
                m = (o > m) ? o : m;
            }
            if (lane == 0) warpmax[ow] = m;
        }
        __syncthreads();
    }
}

// ---------------- kernel 7: fill output with v-mean ------------------------------
__global__ void fill_kernel(float* __restrict__ out) {
    size_t f = (size_t)blockIdx.x * 256 + threadIdx.x;
    int d4 = (int)(f & (DD / 4 - 1));
    size_t row = f >> 7;
    int b = (int)(row >> 11);
    float4 val = *(const float4*)(g_vmean + b * DD + d4 * 4);
    ((float4*)out)[f] = val;
}

// ---------------- kernel 8: logits S1 = q_bar @ k^T * scale ----------------------
__global__ void __launch_bounds__(256)
logits_kernel(const float* __restrict__ q, const float* __restrict__ k) {
    int b = blockIdx.y;
    int n0 = blockIdx.x * 64;
    __shared__ int   tix[UQ];
    __shared__ float qs2[16][64];
    __shared__ float ks2[16][64];
    int tid = threadIdx.x;
    if (tid < UQ) tix[tid] = g_topidx[b * UQ + tid];

    int tx = tid & 15, ty = tid >> 4;
    float acc[4][4];
#pragma unroll
    for (int i = 0; i < 4; i++)
#pragma unroll
        for (int j = 0; j < 4; j++) acc[i][j] = 0.f;

    const float* qb = q + (size_t)b * QQ * DD;
    const float* kb = k + (size_t)b * KVN * DD;

    for (int dt = 0; dt < DD; dt += 16) {
        __syncthreads();
        if (tid < 240) {
            int i = tid >> 2, hh = (tid & 3) * 4;
            float4 v4 = *(const float4*)(qb + (size_t)tix[i] * DD + dt + hh);
            qs2[hh + 0][i] = v4.x; qs2[hh + 1][i] = v4.y;
            qs2[hh + 2][i] = v4.z; qs2[hh + 3][i] = v4.w;
        }
        {
            int r2 = tid >> 2, h2 = (tid & 3) * 4;
            float4 a4 = *(const float4*)(kb + (size_t)(n0 + r2) * DD + dt + h2);
            ks2[h2 + 0][r2] = a4.x; ks2[h2 + 1][r2] = a4.y;
            ks2[h2 + 2][r2] = a4.z; ks2[h2 + 3][r2] = a4.w;
        }
        __syncthreads();
#pragma unroll
        for (int kk = 0; kk < 16; kk++) {
            float a[4], bb[4];
            *(float4*)&a[0]  = *(float4*)&qs2[kk][ty * 4];
            *(float4*)&bb[0] = *(float4*)&ks2[kk][tx * 4];
#pragma unroll
            for (int i = 0; i < 4; i++)
#pragma unroll
                for (int j = 0; j < 4; j++)
                    acc[i][j] += a[i] * bb[j];
        }
    }
    float scale = rsqrtf((float)KVN);
#pragma unroll
    for (int ii = 0; ii < 4; ii++) {
        int i = ty * 4 + ii;
        if (i < UQ) {
#pragma unroll
            for (int j = 0; j < 4; j++)
                g_S1[((size_t)b * UQ + i) * KVN + n0 + tx * 4 + j] =
                    acc[ii][j] * scale;
        }
    }
}

// ---------------- kernel 9: row softmax ------------------------------------------
__global__ void softmax_kernel() {
    int row = blockIdx.x;
    float* p = g_S1 + (size_t)row * KVN;
    __shared__ float sred[256];
    int tid = threadIdx.x;

    float m = -3.4e38f;
    for (int i = tid; i < KVN; i += 256) m = fmaxf(m, p[i]);
    sred[tid] = m; __syncthreads();
    for (int s = 128; s > 0; s >>= 1) {
        if (tid < s) sred[tid] = fmaxf(sred[tid], sred[tid + s]);
        __syncthreads();
    }
    m = sred[0];
    __syncthreads();

    float sum = 0.f;
    for (int i = tid; i < KVN; i += 256) {
        float e = expf(p[i] - m);
        p[i] = e;
        sum += e;
    }
    sred[tid] = sum; __syncthreads();
    for (int s = 128; s > 0; s >>= 1) {
        if (tid < s) sred[tid] += sred[tid + s];
        __syncthreads();
    }
    float inv = 1.0f / sred[0];
    for (int i = tid; i < KVN; i += 256) p[i] *= inv;
}

// ---------------- kernel 10: O partials = P @ V (split kv, PVS=16) ---------------
__global__ void __launch_bounds__(256)
pv_kernel(const float* __restrict__ v) {
    int b = blockIdx.z;
    int s = blockIdx.y;
    int d0 = blockIdx.x * 128;
    int kv0 = s * (KVN / PVS);     // 128

    __shared__ float ps[16][64];
    __shared__ float vs[16][128];
    int tid = threadIdx.x;
    int tx = tid & 15, ty = tid >> 4;
    float acc[4][8];
#pragma unroll
    for (int i = 0; i < 4; i++)
#pragma unroll
        for (int j = 0; j < 8; j++) acc[i][j] = 0.f;

    const float* vb = v + (size_t)b * KVN * DD;

    for (int kt = 0; kt < KVN / PVS; kt += 16) {
        __syncthreads();
        if (tid < 240) {
            int i = tid >> 2, hh = (tid & 3) * 4;
            float4 a4 = *(const float4*)(g_S1 + ((size_t)b * UQ + i) * KVN
                                         + kv0 + kt + hh);
            ps[hh + 0][i] = a4.x; ps[hh + 1][i] = a4.y;
            ps[hh + 2][i] = a4.z; ps[hh + 3][i] = a4.w;
        }
        {
            int kkr = tid >> 4, dc = (tid & 15) * 8;
            float4 a4 = *(const float4*)(vb + (size_t)(kv0 + kt + kkr) * DD + d0 + dc);
            float4 b4 = *(const float4*)(vb + (size_t)(kv0 + kt + kkr) * DD + d0 + dc + 4);
            vs[kkr][dc + 0] = a4.x; vs[kkr][dc + 1] = a4.y;
            vs[kkr][dc + 2] = a4.z; vs[kkr][dc + 3] = a4.w;
            vs[kkr][dc + 4] = b4.x; vs[kkr][dc + 5] = b4.y;
            vs[kkr][dc + 6] = b4.z; vs[kkr][dc + 7] = b4.w;
        }
        __syncthreads();
#pragma unroll
        for (int kk = 0; kk < 16; kk++) {
            float a[4], bb[8];
            *(float4*)&a[0]  = *(float4*)&ps[kk][ty * 4];
            *(float4*)&bb[0] = *(float4*)&vs[kk][tx * 8];
            *(float4*)&bb[4] = *(float4*)&vs[kk][tx * 8 + 4];
#pragma unroll
            for (int i = 0; i < 4; i++)
#pragma unroll
                for (int j = 0; j < 8; j++)
                    acc[i][j] += a[i] * bb[j];
        }
    }
#pragma unroll
    for (int ii = 0; ii < 4; ii++) {
        int i = ty * 4 + ii;
        if (i < UQ) {
#pragma unroll
            for (int j = 0; j < 8; j++)
                g_Opart[(((size_t)s * BB + b) * UQ + i) * DD + d0 + tx * 8 + j] =
                    acc[ii][j];
        }
    }
}

// ---------------- kernel 11: reduce PV partials + scatter ------------------------
__global__ void oreduce_kernel(float* __restrict__ out) {
    int idx = blockIdx.x * 256 + threadIdx.x;
    if (idx >= BB * UQ * DD) return;
    int d = idx % DD;
    int rest = idx / DD;
    int i = rest % UQ;
    int b = rest / UQ;
    float s = 0.f;
#pragma unroll
    for (int p = 0; p < PVS; p++)
        s += g_Opart[(((size_t)p * BB + b) * UQ + i) * DD + d];
    int row = g_topidx[b * UQ + i];
    out[((size_t)b * QQ + row) * DD + d] = s;
}

// ---------------- launch ----------------------------------------------------------
extern "C" void kernel_launch(void* const* d_in, const int* in_sizes, int n_in,
                              void* d_out, int out_size) {
    const float* q    = (const float*)d_in[0];
    const float* k    = (const float*)d_in[1];
    const float* v    = (const float*)d_in[2];
    const int*   sidx = (const int*)d_in[3];
    float* out = (float*)d_out;
    int U = in_sizes[3] / BB;

    split_zero_kernel<<<(BB * QQ * DD / 4) / 256, 256>>>(q, k);
    count_kernel<<<(BB * U + 255) / 256, 256>>>(sidx, U);
    wsum_part_kernel<<<dim3(WS_SPLIT, BB), 512>>>(k, v);
    qkmax_tc_kernel<<<dim3(QQ / 128, KVN / 128, BB), 256>>>();
    wsum_reduce_kernel<<<8, 64>>>();
    refine_kernel<<<(BB * QQ) / 8, 256>>>(q, k, (float)U);
    topk_kernel<<<BB, 1024>>>();
    fill_kernel<<<(BB * QQ * DD / 4) / 256, 256>>>(out);
    logits_kernel<<<dim3(KVN / 64, BB), 256>>>(q, k);
    softmax_kernel<<<BB * UQ, 256>>>();
    pv_kernel<<<dim3(DD / 128, PVS, BB), 256>>>(v);
    oreduce_kernel<<<(BB * UQ * DD + 255) / 256, 256>>>(out);
}